// round 5
// baseline (speedup 1.0000x reference)
#include <cuda_runtime.h>
#include <cuda_fp16.h>
#include <cstdint>
#include <cstddef>

#define NE 2048
#define NH 16
#define HD 128
#define SB 2048
#define NB 2
#define MT 4096   // NB*SB

// ---------------- scratch (__device__ globals; no allocs) ------------------
__device__ __half g_xh  [MT * NE];       // fp16 activations
__device__ __half g_qh  [MT * NE];       // fp16 Q (pre-scaled), [B,S,H*D]
__device__ __half g_kvh [MT * 256];      // fp16 fused K|V, row stride 256
__device__ __half g_aoh [MT * NE];       // attention out fp16
__device__ __half g_wqh [NE * NE];       // Wq * scale
__device__ __half g_wkvh[256 * NE];      // Wk rows 0-127, Wv rows 128-255
__device__ __half g_woh [NE * NE];
__device__ float  g_bqs [NE];            // bq * scale
__device__ float  g_bkv [256];           // bk|bv concat

// ---------------- PTX helpers (sm_80-safe; no 'a' features) ----------------
#define CP16(sa, g)  asm volatile("cp.async.cg.shared.global [%0], [%1], 16;" :: "r"(sa), "l"(g))
#define CP_COMMIT()  asm volatile("cp.async.commit_group;" ::: "memory")
#define CP_WAIT1()   asm volatile("cp.async.wait_group 1;" ::: "memory")
#define CP_WAIT0()   asm volatile("cp.async.wait_group 0;" ::: "memory")

#define LDSM_X4(r0,r1,r2,r3, addr) \
    asm volatile("ldmatrix.sync.aligned.m8n8.x4.shared.b16 {%0,%1,%2,%3}, [%4];" \
        : "=r"(r0),"=r"(r1),"=r"(r2),"=r"(r3) : "r"(addr))
#define LDSM_X4T(r0,r1,r2,r3, addr) \
    asm volatile("ldmatrix.sync.aligned.m8n8.x4.trans.shared.b16 {%0,%1,%2,%3}, [%4];" \
        : "=r"(r0),"=r"(r1),"=r"(r2),"=r"(r3) : "r"(addr))
#define LDSM_X2(r0,r1, addr) \
    asm volatile("ldmatrix.sync.aligned.m8n8.x2.shared.b16 {%0,%1}, [%2];" \
        : "=r"(r0),"=r"(r1) : "r"(addr))
#define MMA16816(c0,c1,c2,c3, a0,a1,a2,a3, b0,b1) \
    asm volatile("mma.sync.aligned.m16n8k16.row.col.f32.f16.f16.f32 " \
        "{%0,%1,%2,%3}, {%4,%5,%6,%7}, {%8,%9}, {%0,%1,%2,%3};" \
        : "+f"(c0),"+f"(c1),"+f"(c2),"+f"(c3) \
        : "r"(a0),"r"(a1),"r"(a2),"r"(a3),"r"(b0),"r"(b1))

__device__ __forceinline__ uint32_t smem_u32(const void* p) {
    return (uint32_t)__cvta_generic_to_shared(p);
}
__device__ __forceinline__ uint32_t pack_h2(float a, float b) {
    __half2 h = __floats2half2_rn(a, b);
    return *(uint32_t*)&h;
}

// ---------------- fused conversion kernels ----------------------------------
// All weights in one launch: Wq*scale -> wqh, Wk|Wv -> wkvh, Wo -> woh.
__global__ void __launch_bounds__(256)
conv_weights(const float* __restrict__ Wq, const float* __restrict__ Wk,
             const float* __restrict__ Wv, const float* __restrict__ Wo,
             __half* __restrict__ wqh, __half* __restrict__ wkvh,
             __half* __restrict__ woh, float scale)
{
    constexpr int S0 = NE * NE;
    constexpr int S1 = S0 + HD * NE;
    constexpr int S2 = S1 + HD * NE;
    constexpr int S3 = S2 + NE * NE;
    const int i = (blockIdx.x * 256 + threadIdx.x) * 4;
    if (i < S0) {
        float4 v = *(const float4*)(Wq + i);
        __half2* o = (__half2*)(wqh + i);
        o[0] = __floats2half2_rn(v.x * scale, v.y * scale);
        o[1] = __floats2half2_rn(v.z * scale, v.w * scale);
    } else if (i < S1) {
        const int j = i - S0;
        float4 v = *(const float4*)(Wk + j);
        __half2* o = (__half2*)(wkvh + j);
        o[0] = __floats2half2_rn(v.x, v.y);
        o[1] = __floats2half2_rn(v.z, v.w);
    } else if (i < S2) {
        const int j = i - S1;
        float4 v = *(const float4*)(Wv + j);
        __half2* o = (__half2*)(wkvh + HD * NE + j);
        o[0] = __floats2half2_rn(v.x, v.y);
        o[1] = __floats2half2_rn(v.z, v.w);
    } else if (i < S3) {
        const int j = i - S2;
        float4 v = *(const float4*)(Wo + j);
        __half2* o = (__half2*)(woh + j);
        o[0] = __floats2half2_rn(v.x, v.y);
        o[1] = __floats2half2_rn(v.z, v.w);
    }
}

__global__ void __launch_bounds__(256)
conv_bias(const float* __restrict__ bq, const float* __restrict__ bk,
          const float* __restrict__ bv, float* __restrict__ bqs,
          float* __restrict__ bkv, float scale)
{
    const int t = blockIdx.x * 256 + threadIdx.x;
    if (t < NE) bqs[t] = bq[t] * scale;
    if (t < 128) bkv[t] = bk[t];
    else if (t < 256) bkv[t] = bv[t - 128];
}

__global__ void __launch_bounds__(256)
conv_x(const float* __restrict__ in, __half* __restrict__ out, int n)
{
    int i = (blockIdx.x * 256 + threadIdx.x) * 4;
    if (i < n) {
        float4 v = *(const float4*)(in + i);
        __half2* o = (__half2*)(out + i);
        o[0] = __floats2half2_rn(v.x, v.y);
        o[1] = __floats2half2_rn(v.z, v.w);
    }
}

// ---------------------------------------------------------------------------
// HMMA GEMM (128x128 tile): used for the narrow KV projection (N=256).
// ---------------------------------------------------------------------------
#define PAD 40
#define STG (128 * PAD)
#define AOFF(st) ((st) * STG * 2)
#define BOFF(st) (3 * STG * 2 + (st) * STG * 2)
#define GEMM_SMEM (6 * STG * 2)

template<typename OutT>
__global__ void __launch_bounds__(256)
gemm_hmma(const __half* __restrict__ A, const __half* __restrict__ B,
          const float* __restrict__ bias, OutT* __restrict__ C,
          int M, int N, int K)
{
    extern __shared__ __half sh[];
    const uint32_t smb = smem_u32(sh);

    const int tid  = threadIdx.x;
    const int wid  = tid >> 5;
    const int lane = tid & 31;
    const int bm = blockIdx.y * 128;
    const int bn = blockIdx.x * 128;
    const int m0 = (wid >> 2) * 64;
    const int n0 = (wid & 3) * 32;

    const int lrow = tid >> 2;
    const int lch  = tid & 3;

    float c[4][4][4];
    #pragma unroll
    for (int mt = 0; mt < 4; mt++)
        #pragma unroll
        for (int nt = 0; nt < 4; nt++)
            #pragma unroll
            for (int r = 0; r < 4; r++) c[mt][nt][r] = 0.f;

    const __half* Ab = A + (size_t)bm * K;
    const __half* Bb = B + (size_t)bn * K;
    const int nk = K / 32;

    auto load_stage = [&](int st, int k0) {
        #pragma unroll
        for (int r = 0; r < 2; r++) {
            const int row = lrow + r * 64;
            const uint32_t so = (uint32_t)(row * PAD + lch * 8) * 2;
            CP16(smb + AOFF(st) + so, Ab + (size_t)row * K + k0 + lch * 8);
            CP16(smb + BOFF(st) + so, Bb + (size_t)row * K + k0 + lch * 8);
        }
    };

    load_stage(0, 0);  CP_COMMIT();
    load_stage(1, 32); CP_COMMIT();

    const int a_r = lane & 15, a_c = (lane >> 4) * 8;
    const int b_r = lane & 7,  b_c = ((lane >> 3) & 1) * 8;

    for (int i = 0; i < nk; i++) {
        CP_WAIT1();
        __syncthreads();
        if (i + 2 < nk) load_stage((i + 2) % 3, (i + 2) * 32);
        CP_COMMIT();

        const int st = i % 3;
        #pragma unroll
        for (int ks = 0; ks < 2; ks++) {
            uint32_t a[4][4], b[4][2];
            #pragma unroll
            for (int mt = 0; mt < 4; mt++) {
                const uint32_t addr = smb + AOFF(st) +
                    (uint32_t)((m0 + mt * 16 + a_r) * PAD + ks * 16 + a_c) * 2;
                LDSM_X4(a[mt][0], a[mt][1], a[mt][2], a[mt][3], addr);
            }
            #pragma unroll
            for (int nt = 0; nt < 4; nt++) {
                const uint32_t addr = smb + BOFF(st) +
                    (uint32_t)((n0 + nt * 8 + b_r) * PAD + ks * 16 + b_c) * 2;
                LDSM_X2(b[nt][0], b[nt][1], addr);
            }
            #pragma unroll
            for (int mt = 0; mt < 4; mt++)
                #pragma unroll
                for (int nt = 0; nt < 4; nt++)
                    MMA16816(c[mt][nt][0], c[mt][nt][1], c[mt][nt][2], c[mt][nt][3],
                             a[mt][0], a[mt][1], a[mt][2], a[mt][3],
                             b[nt][0], b[nt][1]);
        }
        __syncthreads();
    }

    const int tr  = lane >> 2;
    const int tc2 = (lane & 3) * 2;
    #pragma unroll
    for (int mt = 0; mt < 4; mt++) {
        const int r0 = bm + m0 + mt * 16 + tr;
        #pragma unroll
        for (int nt = 0; nt < 4; nt++) {
            const int cc = bn + n0 + nt * 8 + tc2;
            const float bx = bias[cc], by = bias[cc + 1];
            if constexpr (sizeof(OutT) == 4) {
                *(float2*)&C[(size_t)r0 * N + cc] =
                    make_float2(c[mt][nt][0] + bx, c[mt][nt][1] + by);
                *(float2*)&C[(size_t)(r0 + 8) * N + cc] =
                    make_float2(c[mt][nt][2] + bx, c[mt][nt][3] + by);
            } else {
                *(__half2*)&C[(size_t)r0 * N + cc] =
                    __floats2half2_rn(c[mt][nt][0] + bx, c[mt][nt][1] + by);
                *(__half2*)&C[(size_t)(r0 + 8) * N + cc] =
                    __floats2half2_rn(c[mt][nt][2] + bx, c[mt][nt][3] + by);
            }
        }
    }
}

// ---------------------------------------------------------------------------
// HMMA GEMM (128x256 tile, warp tile 64x64): for the two big N=2048 GEMMs.
// 256 threads / 8 warps (2x4). BK=32, 3-stage cp.async pipeline.
// Per k16 per warp: 4 LDSM_X4 (A) + 4 LDSM_X4 (B) feed 32 MMAs.
// ---------------------------------------------------------------------------
#define ASTG (128 * PAD)
#define BSTG (256 * PAD)
#define AOFF2(st) ((st) * ASTG * 2)
#define BOFF2(st) (3 * ASTG * 2 + (st) * BSTG * 2)
#define GEMM2_SMEM (3 * (ASTG + BSTG) * 2)    // 92160 B

template<typename OutT>
__global__ void __launch_bounds__(256, 1)
gemm_hmma_n256(const __half* __restrict__ A, const __half* __restrict__ B,
               const float* __restrict__ bias, OutT* __restrict__ C,
               int M, int N, int K)
{
    extern __shared__ __half sh[];
    const uint32_t smb = smem_u32(sh);

    const int tid  = threadIdx.x;
    const int wid  = tid >> 5;
    const int lane = tid & 31;
    const int bm = blockIdx.y * 128;
    const int bn = blockIdx.x * 256;
    const int m0 = (wid >> 2) * 64;     // 0 or 64
    const int n0 = (wid & 3) * 64;      // 0..192

    const int lrow = tid >> 2;          // 0..63
    const int lch  = tid & 3;

    float c[4][8][4];
    #pragma unroll
    for (int mt = 0; mt < 4; mt++)
        #pragma unroll
        for (int nt = 0; nt < 8; nt++)
            #pragma unroll
            for (int r = 0; r < 4; r++) c[mt][nt][r] = 0.f;

    const __half* Ab = A + (size_t)bm * K;
    const __half* Bb = B + (size_t)bn * K;
    const int nk = K / 32;

    auto load_stage = [&](int st, int k0) {
        #pragma unroll
        for (int r = 0; r < 2; r++) {
            const int row = lrow + r * 64;
            const uint32_t so = (uint32_t)(row * PAD + lch * 8) * 2;
            CP16(smb + AOFF2(st) + so, Ab + (size_t)row * K + k0 + lch * 8);
        }
        #pragma unroll
        for (int r = 0; r < 4; r++) {
            const int row = lrow + r * 64;
            const uint32_t so = (uint32_t)(row * PAD + lch * 8) * 2;
            CP16(smb + BOFF2(st) + so, Bb + (size_t)row * K + k0 + lch * 8);
        }
    };

    load_stage(0, 0);  CP_COMMIT();
    load_stage(1, 32); CP_COMMIT();

    const int a_r = lane & 15, a_c = (lane >> 4) * 8;
    const int b_row = ((lane >> 4) << 3) + (lane & 7);
    const int b_col = ((lane >> 3) & 1) * 8;

    for (int i = 0; i < nk; i++) {
        CP_WAIT1();
        __syncthreads();
        if (i + 2 < nk) load_stage((i + 2) % 3, (i + 2) * 32);
        CP_COMMIT();

        const int st = i % 3;
        #pragma unroll
        for (int ks = 0; ks < 2; ks++) {
            uint32_t a[4][4], b[8][2];
            #pragma unroll
            for (int mt = 0; mt < 4; mt++) {
                const uint32_t addr = smb + AOFF2(st) +
                    (uint32_t)((m0 + mt * 16 + a_r) * PAD + ks * 16 + a_c) * 2;
                LDSM_X4(a[mt][0], a[mt][1], a[mt][2], a[mt][3], addr);
            }
            #pragma unroll
            for (int np = 0; np < 4; np++) {
                const uint32_t addr = smb + BOFF2(st) +
                    (uint32_t)((n0 + np * 16 + b_row) * PAD + ks * 16 + b_col) * 2;
                LDSM_X4(b[2*np][0], b[2*np][1], b[2*np+1][0], b[2*np+1][1], addr);
            }
            #pragma unroll
            for (int mt = 0; mt < 4; mt++)
                #pragma unroll
                for (int nt = 0; nt < 8; nt++)
                    MMA16816(c[mt][nt][0], c[mt][nt][1], c[mt][nt][2], c[mt][nt][3],
                             a[mt][0], a[mt][1], a[mt][2], a[mt][3],
                             b[nt][0], b[nt][1]);
        }
        __syncthreads();
    }

    const int tr  = lane >> 2;
    const int tc2 = (lane & 3) * 2;
    #pragma unroll
    for (int mt = 0; mt < 4; mt++) {
        const int r0 = bm + m0 + mt * 16 + tr;
        #pragma unroll
        for (int nt = 0; nt < 8; nt++) {
            const int cc = bn + n0 + nt * 8 + tc2;
            const float bx = bias[cc], by = bias[cc + 1];
            if constexpr (sizeof(OutT) == 4) {
                *(float2*)&C[(size_t)r0 * N + cc] =
                    make_float2(c[mt][nt][0] + bx, c[mt][nt][1] + by);
                *(float2*)&C[(size_t)(r0 + 8) * N + cc] =
                    make_float2(c[mt][nt][2] + bx, c[mt][nt][3] + by);
            } else {
                *(__half2*)&C[(size_t)r0 * N + cc] =
                    __floats2half2_rn(c[mt][nt][0] + bx, c[mt][nt][1] + by);
                *(__half2*)&C[(size_t)(r0 + 8) * N + cc] =
                    __floats2half2_rn(c[mt][nt][2] + bx, c[mt][nt][3] + by);
            }
        }
    }
}

// ---------------------------------------------------------------------------
// HMMA MQA flash attention (unchanged from R4; validated).
// ---------------------------------------------------------------------------
#define ATT_SMEM (43520 * 2)

__global__ void __launch_bounds__(128)
mqa_attn_h(const __half* __restrict__ qh, const __half* __restrict__ kvh,
           __half* __restrict__ ao)
{
    extern __shared__ __half sh[];
    const uint32_t smb = smem_u32(sh);

    const int tid = threadIdx.x, wid = tid >> 5, lane = tid & 31;
    const int qt = gridDim.x - 1 - blockIdx.x;
    const int h = blockIdx.y, b = blockIdx.z;
    const int q0 = qt * 64;
    const int ntk = qt + 1;
    const int gid = lane >> 2, tig = lane & 3;
    const int m0w = wid * 16;

    {
        const __half* qg = qh + (size_t)(b * SB + q0) * NE + h * HD;
        #pragma unroll
        for (int i = 0; i < 8; i++) {
            const int c = i * 128 + tid;
            const int row = c >> 4, ch = c & 15;
            CP16(smb + (uint32_t)(row * 136 + ch * 8) * 2,
                 qg + (size_t)row * NE + ch * 8);
        }
    }
    CP_COMMIT();

    auto load_kv = [&](int jt, int buf) {
        const __half* g = kvh + (size_t)(b * SB + jt * 64) * 256;
        const uint32_t kb = 8704u + (uint32_t)buf * 17408u;
        #pragma unroll
        for (int i = 0; i < 16; i++) {
            const int c = i * 128 + tid;
            const int row = c >> 5, ch = c & 31;
            const uint32_t off = kb + ((ch & 16) ? 8704u : 0u)
                               + (uint32_t)(row * 136 + (ch & 15) * 8);
            CP16(smb + off * 2, g + (size_t)row * 256 + ch * 8);
        }
    };
    load_kv(0, 0);
    CP_COMMIT();
    CP_WAIT0();
    __syncthreads();

    uint32_t qa[8][4];
    {
        const int a_r = lane & 15, a_c = (lane >> 4) * 8;
        #pragma unroll
        for (int kt = 0; kt < 8; kt++) {
            const uint32_t addr = smb +
                (uint32_t)((m0w + a_r) * 136 + kt * 16 + a_c) * 2;
            LDSM_X4(qa[kt][0], qa[kt][1], qa[kt][2], qa[kt][3], addr);
        }
    }

    float co[16][4];
    #pragma unroll
    for (int n = 0; n < 16; n++)
        #pragma unroll
        for (int r = 0; r < 4; r++) co[n][r] = 0.f;
    float m0 = -1e30f, m1 = -1e30f, l0 = 0.f, l1 = 0.f;

    for (int jt = 0; jt < ntk; jt++) {
        if (jt > 0) { CP_WAIT0(); __syncthreads(); }
        if (jt + 1 < ntk) { load_kv(jt + 1, (jt + 1) & 1); CP_COMMIT(); }

        const int buf = jt & 1;
        const uint32_t kbB = smb + (8704u + (uint32_t)buf * 17408u) * 2u;
        const uint32_t vbB = kbB + 8704u * 2u;

        float s[8][4];
        #pragma unroll
        for (int n = 0; n < 8; n++)
            #pragma unroll
            for (int r = 0; r < 4; r++) s[n][r] = 0.f;

        #pragma unroll
        for (int kt = 0; kt < 8; kt++) {
            #pragma unroll
            for (int np = 0; np < 4; np++) {
                uint32_t b0, b1, b2, b3;
                const uint32_t addr = kbB + (uint32_t)(
                    (np * 16 + ((lane >> 4) << 3) + (lane & 7)) * 136
                    + kt * 16 + ((lane >> 3) & 1) * 8) * 2;
                LDSM_X4(b0, b1, b2, b3, addr);
                MMA16816(s[2*np][0], s[2*np][1], s[2*np][2], s[2*np][3],
                         qa[kt][0], qa[kt][1], qa[kt][2], qa[kt][3], b0, b1);
                MMA16816(s[2*np+1][0], s[2*np+1][1], s[2*np+1][2], s[2*np+1][3],
                         qa[kt][0], qa[kt][1], qa[kt][2], qa[kt][3], b2, b3);
            }
        }

        if (jt == ntk - 1) {
            const int r0 = m0w + gid, r1 = r0 + 8;
            #pragma unroll
            for (int nt = 0; nt < 8; nt++) {
                const int c0 = nt * 8 + tig * 2, c1 = c0 + 1;
                if (c0 > r0) s[nt][0] = -1e30f;
                if (c1 > r0) s[nt][1] = -1e30f;
                if (c0 > r1) s[nt][2] = -1e30f;
                if (c1 > r1) s[nt][3] = -1e30f;
            }
        }

        float mx0 = -1e30f, mx1 = -1e30f;
        #pragma unroll
        for (int nt = 0; nt < 8; nt++) {
            mx0 = fmaxf(mx0, fmaxf(s[nt][0], s[nt][1]));
            mx1 = fmaxf(mx1, fmaxf(s[nt][2], s[nt][3]));
        }
        mx0 = fmaxf(mx0, __shfl_xor_sync(0xffffffffu, mx0, 1));
        mx0 = fmaxf(mx0, __shfl_xor_sync(0xffffffffu, mx0, 2));
        mx1 = fmaxf(mx1, __shfl_xor_sync(0xffffffffu, mx1, 1));
        mx1 = fmaxf(mx1, __shfl_xor_sync(0xffffffffu, mx1, 2));

        const float mn0 = fmaxf(m0, mx0), mn1 = fmaxf(m1, mx1);
        const float al0 = __expf(m0 - mn0), al1 = __expf(m1 - mn1);
        float ls0 = 0.f, ls1 = 0.f;
        #pragma unroll
        for (int nt = 0; nt < 8; nt++) {
            s[nt][0] = __expf(s[nt][0] - mn0);
            s[nt][1] = __expf(s[nt][1] - mn0);
            s[nt][2] = __expf(s[nt][2] - mn1);
            s[nt][3] = __expf(s[nt][3] - mn1);
            ls0 += s[nt][0] + s[nt][1];
            ls1 += s[nt][2] + s[nt][3];
        }
        ls0 += __shfl_xor_sync(0xffffffffu, ls0, 1);
        ls0 += __shfl_xor_sync(0xffffffffu, ls0, 2);
        ls1 += __shfl_xor_sync(0xffffffffu, ls1, 1);
        ls1 += __shfl_xor_sync(0xffffffffu, ls1, 2);
        l0 = l0 * al0 + ls0;  l1 = l1 * al1 + ls1;
        m0 = mn0;  m1 = mn1;

        #pragma unroll
        for (int nt = 0; nt < 16; nt++) {
            co[nt][0] *= al0; co[nt][1] *= al0;
            co[nt][2] *= al1; co[nt][3] *= al1;
        }

        uint32_t pa[4][4];
        #pragma unroll
        for (int t = 0; t < 4; t++) {
            pa[t][0] = pack_h2(s[2*t][0],   s[2*t][1]);
            pa[t][1] = pack_h2(s[2*t][2],   s[2*t][3]);
            pa[t][2] = pack_h2(s[2*t+1][0], s[2*t+1][1]);
            pa[t][3] = pack_h2(s[2*t+1][2], s[2*t+1][3]);
        }

        #pragma unroll
        for (int t = 0; t < 4; t++) {
            #pragma unroll
            for (int dp = 0; dp < 8; dp++) {
                uint32_t b0, b1, b2, b3;
                const uint32_t addr = vbB + (uint32_t)(
                    (t * 16 + ((lane >> 3) & 1) * 8 + (lane & 7)) * 136
                    + dp * 16 + (lane >> 4) * 8) * 2;
                LDSM_X4T(b0, b1, b2, b3, addr);
                MMA16816(co[2*dp][0], co[2*dp][1], co[2*dp][2], co[2*dp][3],
                         pa[t][0], pa[t][1], pa[t][2], pa[t][3], b0, b1);
                MMA16816(co[2*dp+1][0], co[2*dp+1][1], co[2*dp+1][2], co[2*dp+1][3],
                         pa[t][0], pa[t][1], pa[t][2], pa[t][3], b2, b3);
            }
        }
    }

    const float inv0 = 1.f / l0, inv1 = 1.f / l1;
    const int r0 = q0 + m0w + gid, r1 = r0 + 8;
    __half* o0 = ao + (size_t)(b * SB + r0) * NE + h * HD;
    __half* o1 = ao + (size_t)(b * SB + r1) * NE + h * HD;
    #pragma unroll
    for (int nt = 0; nt < 16; nt++) {
        const int cc = nt * 8 + tig * 2;
        *(__half2*)(o0 + cc) = __floats2half2_rn(co[nt][0] * inv0, co[nt][1] * inv0);
        *(__half2*)(o1 + cc) = __floats2half2_rn(co[nt][2] * inv1, co[nt][3] * inv1);
    }
}

// ---------------------------------------------------------------------------
extern "C" void kernel_launch(void* const* d_in, const int* in_sizes, int n_in,
                              void* d_out, int out_size)
{
    const float* x  = (const float*)d_in[0];
    const float* Wq = (const float*)d_in[1];
    const float* bq = (const float*)d_in[2];
    const float* Wk = (const float*)d_in[3];
    const float* bk = (const float*)d_in[4];
    const float* Wv = (const float*)d_in[5];
    const float* bv = (const float*)d_in[6];
    const float* Wo = (const float*)d_in[7];
    const float* bo = (const float*)d_in[8];
    float* out = (float*)d_out;

    __half *xh, *qhp, *kvh, *aoh, *wqh, *wkvh, *woh;
    float *bqs, *bkv;
    cudaGetSymbolAddress((void**)&xh,   g_xh);
    cudaGetSymbolAddress((void**)&qhp,  g_qh);
    cudaGetSymbolAddress((void**)&kvh,  g_kvh);
    cudaGetSymbolAddress((void**)&aoh,  g_aoh);
    cudaGetSymbolAddress((void**)&wqh,  g_wqh);
    cudaGetSymbolAddress((void**)&wkvh, g_wkvh);
    cudaGetSymbolAddress((void**)&woh,  g_woh);
    cudaGetSymbolAddress((void**)&bqs,  g_bqs);
    cudaGetSymbolAddress((void**)&bkv,  g_bkv);

    cudaFuncSetAttribute(gemm_hmma<__half>,       cudaFuncAttributeMaxDynamicSharedMemorySize, GEMM_SMEM);
    cudaFuncSetAttribute(gemm_hmma_n256<__half>,  cudaFuncAttributeMaxDynamicSharedMemorySize, GEMM2_SMEM);
    cudaFuncSetAttribute(gemm_hmma_n256<float>,   cudaFuncAttributeMaxDynamicSharedMemorySize, GEMM2_SMEM);
    cudaFuncSetAttribute(mqa_attn_h, cudaFuncAttributeMaxDynamicSharedMemorySize, ATT_SMEM);

    const float scale = 0.08838834764831845f;   // 1/sqrt(128)
    dim3 blk(256);

    // 1: all weights   2: biases   3: x
    constexpr int WTOT = NE * NE + 2 * HD * NE + NE * NE;
    conv_weights<<<WTOT / 1024, blk>>>(Wq, Wk, Wv, Wo, wqh, wkvh, woh, scale);
    conv_bias<<<NE / 256, blk>>>(bq, bk, bv, bqs, bkv, scale);
    conv_x<<<(MT * NE) / 1024, blk>>>(x, xh, MT * NE);

    // 4: Q projection (128x256 tiles)
    gemm_hmma_n256<__half><<<dim3(NE / 256, MT / 128), blk, GEMM2_SMEM>>>(xh, wqh, bqs, qhp, MT, NE, NE);
    // 5: fused K|V projection (128x128 tiles)
    gemm_hmma<__half><<<dim3(256 / 128, MT / 128), blk, GEMM_SMEM>>>(xh, wkvh, bkv, kvh, MT, 256, NE);
    // 6: attention (this is launch #6 -> profiled by ncu -s 5 -c 1)
    mqa_attn_h<<<dim3(SB / 64, NH, NB), dim3(128), ATT_SMEM>>>(qhp, kvh, aoh);
    // 7: output projection (128x256 tiles)
    gemm_hmma_n256<float><<<dim3(NE / 256, MT / 128), blk, GEMM2_SMEM>>>(aoh, woh, bo, out, MT, NE, NE);
}

// round 6
// speedup vs baseline: 1.0343x; 1.0343x over previous
#include <cuda_runtime.h>
#include <cuda_fp16.h>
#include <cstdint>
#include <cstddef>

#define NE 2048
#define NH 16
#define HD 128
#define SB 2048
#define NB 2
#define MT 4096   // NB*SB

// ---------------- scratch (__device__ globals; no allocs) ------------------
__device__ __half g_xh  [MT * NE];       // fp16 activations
__device__ __half g_qh  [MT * NE];       // fp16 Q (pre-scaled), [B,S,H*D]
__device__ __half g_kvh [MT * 256];      // fp16 fused K|V, row stride 256
__device__ __half g_aoh [MT * NE];       // attention out fp16
__device__ __half g_wqh [NE * NE];       // Wq * scale
__device__ __half g_wkvh[256 * NE];      // Wk rows 0-127, Wv rows 128-255
__device__ __half g_woh [NE * NE];
__device__ float  g_bqs [NE];            // bq * scale
__device__ float  g_bkv [256];           // bk|bv concat

// ---------------- PTX helpers (sm_80-safe; no 'a' features) ----------------
#define CP16(sa, g)  asm volatile("cp.async.cg.shared.global [%0], [%1], 16;" :: "r"(sa), "l"(g))
#define CP_COMMIT()  asm volatile("cp.async.commit_group;" ::: "memory")
#define CP_WAIT1()   asm volatile("cp.async.wait_group 1;" ::: "memory")
#define CP_WAIT0()   asm volatile("cp.async.wait_group 0;" ::: "memory")

#define LDSM_X4(r0,r1,r2,r3, addr) \
    asm volatile("ldmatrix.sync.aligned.m8n8.x4.shared.b16 {%0,%1,%2,%3}, [%4];" \
        : "=r"(r0),"=r"(r1),"=r"(r2),"=r"(r3) : "r"(addr))
#define LDSM_X4T(r0,r1,r2,r3, addr) \
    asm volatile("ldmatrix.sync.aligned.m8n8.x4.trans.shared.b16 {%0,%1,%2,%3}, [%4];" \
        : "=r"(r0),"=r"(r1),"=r"(r2),"=r"(r3) : "r"(addr))
#define LDSM_X2(r0,r1, addr) \
    asm volatile("ldmatrix.sync.aligned.m8n8.x2.shared.b16 {%0,%1}, [%2];" \
        : "=r"(r0),"=r"(r1) : "r"(addr))
#define MMA16816(c0,c1,c2,c3, a0,a1,a2,a3, b0,b1) \
    asm volatile("mma.sync.aligned.m16n8k16.row.col.f32.f16.f16.f32 " \
        "{%0,%1,%2,%3}, {%4,%5,%6,%7}, {%8,%9}, {%0,%1,%2,%3};" \
        : "+f"(c0),"+f"(c1),"+f"(c2),"+f"(c3) \
        : "r"(a0),"r"(a1),"r"(a2),"r"(a3),"r"(b0),"r"(b1))

__device__ __forceinline__ uint32_t smem_u32(const void* p) {
    return (uint32_t)__cvta_generic_to_shared(p);
}
__device__ __forceinline__ uint32_t pack_h2(float a, float b) {
    __half2 h = __floats2half2_rn(a, b);
    return *(uint32_t*)&h;
}

// ---------------- fused conversion kernels ----------------------------------
__global__ void __launch_bounds__(256)
conv_weights(const float* __restrict__ Wq, const float* __restrict__ Wk,
             const float* __restrict__ Wv, const float* __restrict__ Wo,
             __half* __restrict__ wqh, __half* __restrict__ wkvh,
             __half* __restrict__ woh, float scale)
{
    constexpr int S0 = NE * NE;
    constexpr int S1 = S0 + HD * NE;
    constexpr int S2 = S1 + HD * NE;
    constexpr int S3 = S2 + NE * NE;
    const int i = (blockIdx.x * 256 + threadIdx.x) * 4;
    if (i < S0) {
        float4 v = *(const float4*)(Wq + i);
        __half2* o = (__half2*)(wqh + i);
        o[0] = __floats2half2_rn(v.x * scale, v.y * scale);
        o[1] = __floats2half2_rn(v.z * scale, v.w * scale);
    } else if (i < S1) {
        const int j = i - S0;
        float4 v = *(const float4*)(Wk + j);
        __half2* o = (__half2*)(wkvh + j);
        o[0] = __floats2half2_rn(v.x, v.y);
        o[1] = __floats2half2_rn(v.z, v.w);
    } else if (i < S2) {
        const int j = i - S1;
        float4 v = *(const float4*)(Wv + j);
        __half2* o = (__half2*)(wkvh + HD * NE + j);
        o[0] = __floats2half2_rn(v.x, v.y);
        o[1] = __floats2half2_rn(v.z, v.w);
    } else if (i < S3) {
        const int j = i - S2;
        float4 v = *(const float4*)(Wo + j);
        __half2* o = (__half2*)(woh + j);
        o[0] = __floats2half2_rn(v.x, v.y);
        o[1] = __floats2half2_rn(v.z, v.w);
    }
}

__global__ void __launch_bounds__(256)
conv_bias(const float* __restrict__ bq, const float* __restrict__ bk,
          const float* __restrict__ bv, float* __restrict__ bqs,
          float* __restrict__ bkv, float scale)
{
    const int t = blockIdx.x * 256 + threadIdx.x;
    if (t < NE) bqs[t] = bq[t] * scale;
    if (t < 128) bkv[t] = bk[t];
    else if (t < 256) bkv[t] = bv[t - 128];
}

__global__ void __launch_bounds__(256)
conv_x(const float* __restrict__ in, __half* __restrict__ out, int n)
{
    int i = (blockIdx.x * 256 + threadIdx.x) * 4;
    if (i < n) {
        float4 v = *(const float4*)(in + i);
        __half2* o = (__half2*)(out + i);
        o[0] = __floats2half2_rn(v.x, v.y);
        o[1] = __floats2half2_rn(v.z, v.w);
    }
}

// ---------------------------------------------------------------------------
// HMMA GEMM: 128x128 CTA tile, BK=32, 3-stage cp.async pipeline, 256 threads,
// warp tile 64x32. __launch_bounds__(256, 2) caps regs at 128 so 2 CTAs/SM
// co-reside (16 warps) -> covers MMA/ldmatrix latency, raises tensor util.
// ---------------------------------------------------------------------------
#define PAD 40
#define STG (128 * PAD)
#define AOFF(st) ((st) * STG * 2)
#define BOFF(st) (3 * STG * 2 + (st) * STG * 2)
#define GEMM_SMEM (6 * STG * 2)     // 61440 B; x2 CTAs = 122880 <= 228KB

template<typename OutT>
__global__ void __launch_bounds__(256, 2)
gemm_hmma(const __half* __restrict__ A, const __half* __restrict__ B,
          const float* __restrict__ bias, OutT* __restrict__ C,
          int M, int N, int K)
{
    extern __shared__ __half sh[];
    const uint32_t smb = smem_u32(sh);

    const int tid  = threadIdx.x;
    const int wid  = tid >> 5;
    const int lane = tid & 31;
    const int bm = blockIdx.y * 128;
    const int bn = blockIdx.x * 128;
    const int m0 = (wid >> 2) * 64;
    const int n0 = (wid & 3) * 32;

    const int lrow = tid >> 2;
    const int lch  = tid & 3;

    float c[4][4][4];
    #pragma unroll
    for (int mt = 0; mt < 4; mt++)
        #pragma unroll
        for (int nt = 0; nt < 4; nt++)
            #pragma unroll
            for (int r = 0; r < 4; r++) c[mt][nt][r] = 0.f;

    const __half* Ab = A + (size_t)bm * K;
    const __half* Bb = B + (size_t)bn * K;
    const int nk = K / 32;

    auto load_stage = [&](int st, int k0) {
        #pragma unroll
        for (int r = 0; r < 2; r++) {
            const int row = lrow + r * 64;
            const uint32_t so = (uint32_t)(row * PAD + lch * 8) * 2;
            CP16(smb + AOFF(st) + so, Ab + (size_t)row * K + k0 + lch * 8);
            CP16(smb + BOFF(st) + so, Bb + (size_t)row * K + k0 + lch * 8);
        }
    };

    load_stage(0, 0);  CP_COMMIT();
    load_stage(1, 32); CP_COMMIT();

    const int a_r = lane & 15, a_c = (lane >> 4) * 8;
    const int b_r = lane & 7,  b_c = ((lane >> 3) & 1) * 8;

    for (int i = 0; i < nk; i++) {
        CP_WAIT1();
        __syncthreads();
        if (i + 2 < nk) load_stage((i + 2) % 3, (i + 2) * 32);
        CP_COMMIT();

        const int st = i % 3;
        #pragma unroll
        for (int ks = 0; ks < 2; ks++) {
            uint32_t a[4][4], b[4][2];
            #pragma unroll
            for (int mt = 0; mt < 4; mt++) {
                const uint32_t addr = smb + AOFF(st) +
                    (uint32_t)((m0 + mt * 16 + a_r) * PAD + ks * 16 + a_c) * 2;
                LDSM_X4(a[mt][0], a[mt][1], a[mt][2], a[mt][3], addr);
            }
            #pragma unroll
            for (int nt = 0; nt < 4; nt++) {
                const uint32_t addr = smb + BOFF(st) +
                    (uint32_t)((n0 + nt * 8 + b_r) * PAD + ks * 16 + b_c) * 2;
                LDSM_X2(b[nt][0], b[nt][1], addr);
            }
            #pragma unroll
            for (int mt = 0; mt < 4; mt++)
                #pragma unroll
                for (int nt = 0; nt < 4; nt++)
                    MMA16816(c[mt][nt][0], c[mt][nt][1], c[mt][nt][2], c[mt][nt][3],
                             a[mt][0], a[mt][1], a[mt][2], a[mt][3],
                             b[nt][0], b[nt][1]);
        }
        __syncthreads();
    }

    const int tr  = lane >> 2;
    const int tc2 = (lane & 3) * 2;
    #pragma unroll
    for (int mt = 0; mt < 4; mt++) {
        const int r0 = bm + m0 + mt * 16 + tr;
        #pragma unroll
        for (int nt = 0; nt < 4; nt++) {
            const int cc = bn + n0 + nt * 8 + tc2;
            const float bx = bias[cc], by = bias[cc + 1];
            if constexpr (sizeof(OutT) == 4) {
                *(float2*)&C[(size_t)r0 * N + cc] =
                    make_float2(c[mt][nt][0] + bx, c[mt][nt][1] + by);
                *(float2*)&C[(size_t)(r0 + 8) * N + cc] =
                    make_float2(c[mt][nt][2] + bx, c[mt][nt][3] + by);
            } else {
                *(__half2*)&C[(size_t)r0 * N + cc] =
                    __floats2half2_rn(c[mt][nt][0] + bx, c[mt][nt][1] + by);
                *(__half2*)&C[(size_t)(r0 + 8) * N + cc] =
                    __floats2half2_rn(c[mt][nt][2] + bx, c[mt][nt][3] + by);
            }
        }
    }
}

// ---------------------------------------------------------------------------
// HMMA MQA flash attention (validated in R4/R5, unchanged).
// ---------------------------------------------------------------------------
#define ATT_SMEM (43520 * 2)

__global__ void __launch_bounds__(128)
mqa_attn_h(const __half* __restrict__ qh, const __half* __restrict__ kvh,
           __half* __restrict__ ao)
{
    extern __shared__ __half sh[];
    const uint32_t smb = smem_u32(sh);

    const int tid = threadIdx.x, wid = tid >> 5, lane = tid & 31;
    const int qt = gridDim.x - 1 - blockIdx.x;
    const int h = blockIdx.y, b = blockIdx.z;
    const int q0 = qt * 64;
    const int ntk = qt + 1;
    const int gid = lane >> 2, tig = lane & 3;
    const int m0w = wid * 16;

    {
        const __half* qg = qh + (size_t)(b * SB + q0) * NE + h * HD;
        #pragma unroll
        for (int i = 0; i < 8; i++) {
            const int c = i * 128 + tid;
            const int row = c >> 4, ch = c & 15;
            CP16(smb + (uint32_t)(row * 136 + ch * 8) * 2,
                 qg + (size_t)row * NE + ch * 8);
        }
    }
    CP_COMMIT();

    auto load_kv = [&](int jt, int buf) {
        const __half* g = kvh + (size_t)(b * SB + jt * 64) * 256;
        const uint32_t kb = 8704u + (uint32_t)buf * 17408u;
        #pragma unroll
        for (int i = 0; i < 16; i++) {
            const int c = i * 128 + tid;
            const int row = c >> 5, ch = c & 31;
            const uint32_t off = kb + ((ch & 16) ? 8704u : 0u)
                               + (uint32_t)(row * 136 + (ch & 15) * 8);
            CP16(smb + off * 2, g + (size_t)row * 256 + ch * 8);
        }
    };
    load_kv(0, 0);
    CP_COMMIT();
    CP_WAIT0();
    __syncthreads();

    uint32_t qa[8][4];
    {
        const int a_r = lane & 15, a_c = (lane >> 4) * 8;
        #pragma unroll
        for (int kt = 0; kt < 8; kt++) {
            const uint32_t addr = smb +
                (uint32_t)((m0w + a_r) * 136 + kt * 16 + a_c) * 2;
            LDSM_X4(qa[kt][0], qa[kt][1], qa[kt][2], qa[kt][3], addr);
        }
    }

    float co[16][4];
    #pragma unroll
    for (int n = 0; n < 16; n++)
        #pragma unroll
        for (int r = 0; r < 4; r++) co[n][r] = 0.f;
    float m0 = -1e30f, m1 = -1e30f, l0 = 0.f, l1 = 0.f;

    for (int jt = 0; jt < ntk; jt++) {
        if (jt > 0) { CP_WAIT0(); __syncthreads(); }
        if (jt + 1 < ntk) { load_kv(jt + 1, (jt + 1) & 1); CP_COMMIT(); }

        const int buf = jt & 1;
        const uint32_t kbB = smb + (8704u + (uint32_t)buf * 17408u) * 2u;
        const uint32_t vbB = kbB + 8704u * 2u;

        float s[8][4];
        #pragma unroll
        for (int n = 0; n < 8; n++)
            #pragma unroll
            for (int r = 0; r < 4; r++) s[n][r] = 0.f;

        #pragma unroll
        for (int kt = 0; kt < 8; kt++) {
            #pragma unroll
            for (int np = 0; np < 4; np++) {
                uint32_t b0, b1, b2, b3;
                const uint32_t addr = kbB + (uint32_t)(
                    (np * 16 + ((lane >> 4) << 3) + (lane & 7)) * 136
                    + kt * 16 + ((lane >> 3) & 1) * 8) * 2;
                LDSM_X4(b0, b1, b2, b3, addr);
                MMA16816(s[2*np][0], s[2*np][1], s[2*np][2], s[2*np][3],
                         qa[kt][0], qa[kt][1], qa[kt][2], qa[kt][3], b0, b1);
                MMA16816(s[2*np+1][0], s[2*np+1][1], s[2*np+1][2], s[2*np+1][3],
                         qa[kt][0], qa[kt][1], qa[kt][2], qa[kt][3], b2, b3);
            }
        }

        if (jt == ntk - 1) {
            const int r0 = m0w + gid, r1 = r0 + 8;
            #pragma unroll
            for (int nt = 0; nt < 8; nt++) {
                const int c0 = nt * 8 + tig * 2, c1 = c0 + 1;
                if (c0 > r0) s[nt][0] = -1e30f;
                if (c1 > r0) s[nt][1] = -1e30f;
                if (c0 > r1) s[nt][2] = -1e30f;
                if (c1 > r1) s[nt][3] = -1e30f;
            }
        }

        float mx0 = -1e30f, mx1 = -1e30f;
        #pragma unroll
        for (int nt = 0; nt < 8; nt++) {
            mx0 = fmaxf(mx0, fmaxf(s[nt][0], s[nt][1]));
            mx1 = fmaxf(mx1, fmaxf(s[nt][2], s[nt][3]));
        }
        mx0 = fmaxf(mx0, __shfl_xor_sync(0xffffffffu, mx0, 1));
        mx0 = fmaxf(mx0, __shfl_xor_sync(0xffffffffu, mx0, 2));
        mx1 = fmaxf(mx1, __shfl_xor_sync(0xffffffffu, mx1, 1));
        mx1 = fmaxf(mx1, __shfl_xor_sync(0xffffffffu, mx1, 2));

        const float mn0 = fmaxf(m0, mx0), mn1 = fmaxf(m1, mx1);
        const float al0 = __expf(m0 - mn0), al1 = __expf(m1 - mn1);
        float ls0 = 0.f, ls1 = 0.f;
        #pragma unroll
        for (int nt = 0; nt < 8; nt++) {
            s[nt][0] = __expf(s[nt][0] - mn0);
            s[nt][1] = __expf(s[nt][1] - mn0);
            s[nt][2] = __expf(s[nt][2] - mn1);
            s[nt][3] = __expf(s[nt][3] - mn1);
            ls0 += s[nt][0] + s[nt][1];
            ls1 += s[nt][2] + s[nt][3];
        }
        ls0 += __shfl_xor_sync(0xffffffffu, ls0, 1);
        ls0 += __shfl_xor_sync(0xffffffffu, ls0, 2);
        ls1 += __shfl_xor_sync(0xffffffffu, ls1, 1);
        ls1 += __shfl_xor_sync(0xffffffffu, ls1, 2);
        l0 = l0 * al0 + ls0;  l1 = l1 * al1 + ls1;
        m0 = mn0;  m1 = mn1;

        #pragma unroll
        for (int nt = 0; nt < 16; nt++) {
            co[nt][0] *= al0; co[nt][1] *= al0;
            co[nt][2] *= al1; co[nt][3] *= al1;
        }

        uint32_t pa[4][4];
        #pragma unroll
        for (int t = 0; t < 4; t++) {
            pa[t][0] = pack_h2(s[2*t][0],   s[2*t][1]);
            pa[t][1] = pack_h2(s[2*t][2],   s[2*t][3]);
            pa[t][2] = pack_h2(s[2*t+1][0], s[2*t+1][1]);
            pa[t][3] = pack_h2(s[2*t+1][2], s[2*t+1][3]);
        }

        #pragma unroll
        for (int t = 0; t < 4; t++) {
            #pragma unroll
            for (int dp = 0; dp < 8; dp++) {
                uint32_t b0, b1, b2, b3;
                const uint32_t addr = vbB + (uint32_t)(
                    (t * 16 + ((lane >> 3) & 1) * 8 + (lane & 7)) * 136
                    + dp * 16 + (lane >> 4) * 8) * 2;
                LDSM_X4T(b0, b1, b2, b3, addr);
                MMA16816(co[2*dp][0], co[2*dp][1], co[2*dp][2], co[2*dp][3],
                         pa[t][0], pa[t][1], pa[t][2], pa[t][3], b0, b1);
                MMA16816(co[2*dp+1][0], co[2*dp+1][1], co[2*dp+1][2], co[2*dp+1][3],
                         pa[t][0], pa[t][1], pa[t][2], pa[t][3], b2, b3);
            }
        }
    }

    const float inv0 = 1.f / l0, inv1 = 1.f / l1;
    const int r0 = q0 + m0w + gid, r1 = r0 + 8;
    __half* o0 = ao + (size_t)(b * SB + r0) * NE + h * HD;
    __half* o1 = ao + (size_t)(b * SB + r1) * NE + h * HD;
    #pragma unroll
    for (int nt = 0; nt < 16; nt++) {
        const int cc = nt * 8 + tig * 2;
        *(__half2*)(o0 + cc) = __floats2half2_rn(co[nt][0] * inv0, co[nt][1] * inv0);
        *(__half2*)(o1 + cc) = __floats2half2_rn(co[nt][2] * inv1, co[nt][3] * inv1);
    }
}

// ---------------------------------------------------------------------------
extern "C" void kernel_launch(void* const* d_in, const int* in_sizes, int n_in,
                              void* d_out, int out_size)
{
    const float* x  = (const float*)d_in[0];
    const float* Wq = (const float*)d_in[1];
    const float* bq = (const float*)d_in[2];
    const float* Wk = (const float*)d_in[3];
    const float* bk = (const float*)d_in[4];
    const float* Wv = (const float*)d_in[5];
    const float* bv = (const float*)d_in[6];
    const float* Wo = (const float*)d_in[7];
    const float* bo = (const float*)d_in[8];
    float* out = (float*)d_out;

    __half *xh, *qhp, *kvh, *aoh, *wqh, *wkvh, *woh;
    float *bqs, *bkv;
    cudaGetSymbolAddress((void**)&xh,   g_xh);
    cudaGetSymbolAddress((void**)&qhp,  g_qh);
    cudaGetSymbolAddress((void**)&kvh,  g_kvh);
    cudaGetSymbolAddress((void**)&aoh,  g_aoh);
    cudaGetSymbolAddress((void**)&wqh,  g_wqh);
    cudaGetSymbolAddress((void**)&wkvh, g_wkvh);
    cudaGetSymbolAddress((void**)&woh,  g_woh);
    cudaGetSymbolAddress((void**)&bqs,  g_bqs);
    cudaGetSymbolAddress((void**)&bkv,  g_bkv);

    cudaFuncSetAttribute(gemm_hmma<__half>, cudaFuncAttributeMaxDynamicSharedMemorySize, GEMM_SMEM);
    cudaFuncSetAttribute(gemm_hmma<float>,  cudaFuncAttributeMaxDynamicSharedMemorySize, GEMM_SMEM);
    cudaFuncSetAttribute(mqa_attn_h, cudaFuncAttributeMaxDynamicSharedMemorySize, ATT_SMEM);

    const float scale = 0.08838834764831845f;   // 1/sqrt(128)
    dim3 blk(256);

    constexpr int WTOT = NE * NE + 2 * HD * NE + NE * NE;
    conv_weights<<<WTOT / 1024, blk>>>(Wq, Wk, Wv, Wo, wqh, wkvh, woh, scale);
    conv_bias<<<NE / 256, blk>>>(bq, bk, bv, bqs, bkv, scale);
    conv_x<<<(MT * NE) / 1024, blk>>>(x, xh, MT * NE);

    // Q projection (128x128 tiles, 2 CTAs/SM)
    gemm_hmma<__half><<<dim3(NE / 128, MT / 128), blk, GEMM_SMEM>>>(xh, wqh, bqs, qhp, MT, NE, NE);
    // fused K|V projection
    gemm_hmma<__half><<<dim3(256 / 128, MT / 128), blk, GEMM_SMEM>>>(xh, wkvh, bkv, kvh, MT, 256, NE);
    // attention
    mqa_attn_h<<<dim3(SB / 64, NH, NB), dim3(128), ATT_SMEM>>>(qhp, kvh, aoh);
    // output projection
    gemm_hmma<float><<<dim3(NE / 128, MT / 128), blk, GEMM_SMEM>>>(aoh, woh, bo, out, MT, NE, NE);
}

// round 7
// speedup vs baseline: 1.2330x; 1.1921x over previous
#include <cuda_runtime.h>
#include <cuda_fp16.h>
#include <cstdint>
#include <cstddef>

#define NE 2048
#define NH 16
#define HD 128
#define SB 2048
#define NB 2
#define MT 4096     // NB*SB
#define NQKV 2304   // 2048 (Q) + 128 (K) + 128 (V)

// ---------------- scratch (__device__ globals; no allocs) ------------------
__device__ __half g_xh   [MT * NE];        // fp16 activations
__device__ __half g_qkvh [MT * NQKV];      // fused Q|K|V output, row stride 2304
__device__ __half g_aoh  [MT * NE];        // attention out fp16
__device__ __half g_wqkvh[NQKV * NE];      // Wq*scale rows 0-2047, Wk 2048-2175, Wv 2176-2303
__device__ __half g_woh  [NE * NE];
__device__ float  g_bqkv [NQKV];           // bq*scale | bk | bv

// ---------------- PTX helpers (sm_80-safe; no 'a' features) ----------------
#define CP16(sa, g)  asm volatile("cp.async.cg.shared.global [%0], [%1], 16;" :: "r"(sa), "l"(g))
#define CP_COMMIT()  asm volatile("cp.async.commit_group;" ::: "memory")
#define CP_WAIT1()   asm volatile("cp.async.wait_group 1;" ::: "memory")
#define CP_WAIT0()   asm volatile("cp.async.wait_group 0;" ::: "memory")

#define LDSM_X4(r0,r1,r2,r3, addr) \
    asm volatile("ldmatrix.sync.aligned.m8n8.x4.shared.b16 {%0,%1,%2,%3}, [%4];" \
        : "=r"(r0),"=r"(r1),"=r"(r2),"=r"(r3) : "r"(addr))
#define LDSM_X4T(r0,r1,r2,r3, addr) \
    asm volatile("ldmatrix.sync.aligned.m8n8.x4.trans.shared.b16 {%0,%1,%2,%3}, [%4];" \
        : "=r"(r0),"=r"(r1),"=r"(r2),"=r"(r3) : "r"(addr))
#define MMA16816(c0,c1,c2,c3, a0,a1,a2,a3, b0,b1) \
    asm volatile("mma.sync.aligned.m16n8k16.row.col.f32.f16.f16.f32 " \
        "{%0,%1,%2,%3}, {%4,%5,%6,%7}, {%8,%9}, {%0,%1,%2,%3};" \
        : "+f"(c0),"+f"(c1),"+f"(c2),"+f"(c3) \
        : "r"(a0),"r"(a1),"r"(a2),"r"(a3),"r"(b0),"r"(b1))

__device__ __forceinline__ uint32_t smem_u32(const void* p) {
    return (uint32_t)__cvta_generic_to_shared(p);
}
__device__ __forceinline__ uint32_t pack_h2(float a, float b) {
    __half2 h = __floats2half2_rn(a, b);
    return *(uint32_t*)&h;
}

// ---------------- fused conversion kernels ----------------------------------
__global__ void __launch_bounds__(256)
conv_weights(const float* __restrict__ Wq, const float* __restrict__ Wk,
             const float* __restrict__ Wv, const float* __restrict__ Wo,
             __half* __restrict__ wqkvh, __half* __restrict__ woh, float scale)
{
    constexpr int S0 = NE * NE;            // Wq
    constexpr int S1 = S0 + HD * NE;       // Wk
    constexpr int S2 = S1 + HD * NE;       // Wv
    constexpr int S3 = S2 + NE * NE;       // Wo
    const int i = (blockIdx.x * 256 + threadIdx.x) * 4;
    if (i < S0) {
        float4 v = *(const float4*)(Wq + i);
        __half2* o = (__half2*)(wqkvh + i);
        o[0] = __floats2half2_rn(v.x * scale, v.y * scale);
        o[1] = __floats2half2_rn(v.z * scale, v.w * scale);
    } else if (i < S1) {
        const int j = i - S0;
        float4 v = *(const float4*)(Wk + j);
        __half2* o = (__half2*)(wqkvh + NE * NE + j);
        o[0] = __floats2half2_rn(v.x, v.y);
        o[1] = __floats2half2_rn(v.z, v.w);
    } else if (i < S2) {
        const int j = i - S1;
        float4 v = *(const float4*)(Wv + j);
        __half2* o = (__half2*)(wqkvh + (NE + HD) * NE + j);
        o[0] = __floats2half2_rn(v.x, v.y);
        o[1] = __floats2half2_rn(v.z, v.w);
    } else if (i < S3) {
        const int j = i - S2;
        float4 v = *(const float4*)(Wo + j);
        __half2* o = (__half2*)(woh + j);
        o[0] = __floats2half2_rn(v.x, v.y);
        o[1] = __floats2half2_rn(v.z, v.w);
    }
}

__global__ void __launch_bounds__(256)
conv_bias(const float* __restrict__ bq, const float* __restrict__ bk,
          const float* __restrict__ bv, float* __restrict__ bqkv, float scale)
{
    const int t = blockIdx.x * 256 + threadIdx.x;
    if (t < NE) bqkv[t] = bq[t] * scale;
    else if (t < NE + HD) bqkv[t] = bk[t - NE];
    else if (t < NQKV) bqkv[t] = bv[t - NE - HD];
}

__global__ void __launch_bounds__(256)
conv_x(const float* __restrict__ in, __half* __restrict__ out, int n)
{
    int i = (blockIdx.x * 256 + threadIdx.x) * 4;
    if (i < n) {
        float4 v = *(const float4*)(in + i);
        __half2* o = (__half2*)(out + i);
        o[0] = __floats2half2_rn(v.x, v.y);
        o[1] = __floats2half2_rn(v.z, v.w);
    }
}

// ---------------------------------------------------------------------------
// HMMA GEMM: 128x128 CTA tile, 128 threads / 4 warps (2x2), warp tile 64x64.
// BK=32, 3-stage cp.async. Warp tile 64x64 halves LDSM bytes/FLOP vs 64x32
// (0.023 vs 0.047 B/FLOP) -> smem port demand ~= MMA demand.
// __launch_bounds__(128,2): reg cap 256 (need ~200) -> 2 CTAs/SM by regs;
// smem 61440*2 = 122880 fits.
// ---------------------------------------------------------------------------
#define PAD 40
#define STG (128 * PAD)
#define AOFF(st) ((st) * STG * 2)
#define BOFF(st) (3 * STG * 2 + (st) * STG * 2)
#define GEMM_SMEM (6 * STG * 2)     // 61440 B

template<typename OutT>
__global__ void __launch_bounds__(128, 2)
gemm_hmma64(const __half* __restrict__ A, const __half* __restrict__ B,
            const float* __restrict__ bias, OutT* __restrict__ C,
            int M, int N, int K)
{
    extern __shared__ __half sh[];
    const uint32_t smb = smem_u32(sh);

    const int tid  = threadIdx.x;
    const int wid  = tid >> 5;
    const int lane = tid & 31;
    const int bm = blockIdx.y * 128;
    const int bn = blockIdx.x * 128;
    const int m0 = (wid >> 1) * 64;
    const int n0 = (wid & 1) * 64;

    const int lrow = tid >> 2;          // 0..31; x4 passes -> 128 rows
    const int lch  = tid & 3;

    float c[4][8][4];
    #pragma unroll
    for (int mt = 0; mt < 4; mt++)
        #pragma unroll
        for (int nt = 0; nt < 8; nt++)
            #pragma unroll
            for (int r = 0; r < 4; r++) c[mt][nt][r] = 0.f;

    const __half* Ab = A + (size_t)bm * K;
    const __half* Bb = B + (size_t)bn * K;
    const int nk = K / 32;

    auto load_stage = [&](int st, int k0) {
        #pragma unroll
        for (int r = 0; r < 4; r++) {
            const int row = lrow + r * 32;
            const uint32_t so = (uint32_t)(row * PAD + lch * 8) * 2;
            CP16(smb + AOFF(st) + so, Ab + (size_t)row * K + k0 + lch * 8);
            CP16(smb + BOFF(st) + so, Bb + (size_t)row * K + k0 + lch * 8);
        }
    };

    load_stage(0, 0);  CP_COMMIT();
    load_stage(1, 32); CP_COMMIT();

    const int a_r = lane & 15, a_c = (lane >> 4) * 8;
    const int b_row = ((lane >> 4) << 3) + (lane & 7);
    const int b_col = ((lane >> 3) & 1) * 8;

    for (int i = 0; i < nk; i++) {
        CP_WAIT1();
        __syncthreads();
        if (i + 2 < nk) load_stage((i + 2) % 3, (i + 2) * 32);
        CP_COMMIT();

        const int st = i % 3;
        #pragma unroll
        for (int ks = 0; ks < 2; ks++) {
            uint32_t a[4][4], b[8][2];
            #pragma unroll
            for (int mt = 0; mt < 4; mt++) {
                const uint32_t addr = smb + AOFF(st) +
                    (uint32_t)((m0 + mt * 16 + a_r) * PAD + ks * 16 + a_c) * 2;
                LDSM_X4(a[mt][0], a[mt][1], a[mt][2], a[mt][3], addr);
            }
            #pragma unroll
            for (int np = 0; np < 4; np++) {
                const uint32_t addr = smb + BOFF(st) +
                    (uint32_t)((n0 + np * 16 + b_row) * PAD + ks * 16 + b_col) * 2;
                LDSM_X4(b[2*np][0], b[2*np][1], b[2*np+1][0], b[2*np+1][1], addr);
            }
            #pragma unroll
            for (int mt = 0; mt < 4; mt++)
                #pragma unroll
                for (int nt = 0; nt < 8; nt++)
                    MMA16816(c[mt][nt][0], c[mt][nt][1], c[mt][nt][2], c[mt][nt][3],
                             a[mt][0], a[mt][1], a[mt][2], a[mt][3],
                             b[nt][0], b[nt][1]);
        }
        __syncthreads();
    }

    const int tr  = lane >> 2;
    const int tc2 = (lane & 3) * 2;
    #pragma unroll
    for (int mt = 0; mt < 4; mt++) {
        const int r0 = bm + m0 + mt * 16 + tr;
        #pragma unroll
        for (int nt = 0; nt < 8; nt++) {
            const int cc = bn + n0 + nt * 8 + tc2;
            const float bx = bias[cc], by = bias[cc + 1];
            if constexpr (sizeof(OutT) == 4) {
                *(float2*)&C[(size_t)r0 * N + cc] =
                    make_float2(c[mt][nt][0] + bx, c[mt][nt][1] + by);
                *(float2*)&C[(size_t)(r0 + 8) * N + cc] =
                    make_float2(c[mt][nt][2] + bx, c[mt][nt][3] + by);
            } else {
                *(__half2*)&C[(size_t)r0 * N + cc] =
                    __floats2half2_rn(c[mt][nt][0] + bx, c[mt][nt][1] + by);
                *(__half2*)&C[(size_t)(r0 + 8) * N + cc] =
                    __floats2half2_rn(c[mt][nt][2] + bx, c[mt][nt][3] + by);
            }
        }
    }
}

// ---------------------------------------------------------------------------
// HMMA MQA flash attention (validated; reads fused QKV buffer, stride 2304).
// ---------------------------------------------------------------------------
#define ATT_SMEM (43520 * 2)

__global__ void __launch_bounds__(128)
mqa_attn_h(const __half* __restrict__ qkv, __half* __restrict__ ao)
{
    extern __shared__ __half sh[];
    const uint32_t smb = smem_u32(sh);

    const int tid = threadIdx.x, wid = tid >> 5, lane = tid & 31;
    const int qt = gridDim.x - 1 - blockIdx.x;
    const int h = blockIdx.y, b = blockIdx.z;
    const int q0 = qt * 64;
    const int ntk = qt + 1;
    const int gid = lane >> 2, tig = lane & 3;
    const int m0w = wid * 16;

    {
        const __half* qg = qkv + (size_t)(b * SB + q0) * NQKV + h * HD;
        #pragma unroll
        for (int i = 0; i < 8; i++) {
            const int c = i * 128 + tid;
            const int row = c >> 4, ch = c & 15;
            CP16(smb + (uint32_t)(row * 136 + ch * 8) * 2,
                 qg + (size_t)row * NQKV + ch * 8);
        }
    }
    CP_COMMIT();

    auto load_kv = [&](int jt, int buf) {
        const __half* g = qkv + (size_t)(b * SB + jt * 64) * NQKV + NE;
        const uint32_t kb = 8704u + (uint32_t)buf * 17408u;
        #pragma unroll
        for (int i = 0; i < 16; i++) {
            const int c = i * 128 + tid;
            const int row = c >> 5, ch = c & 31;
            const uint32_t off = kb + ((ch & 16) ? 8704u : 0u)
                               + (uint32_t)(row * 136 + (ch & 15) * 8);
            CP16(smb + off * 2, g + (size_t)row * NQKV + ch * 8);
        }
    };
    load_kv(0, 0);
    CP_COMMIT();
    CP_WAIT0();
    __syncthreads();

    uint32_t qa[8][4];
    {
        const int a_r = lane & 15, a_c = (lane >> 4) * 8;
        #pragma unroll
        for (int kt = 0; kt < 8; kt++) {
            const uint32_t addr = smb +
                (uint32_t)((m0w + a_r) * 136 + kt * 16 + a_c) * 2;
            LDSM_X4(qa[kt][0], qa[kt][1], qa[kt][2], qa[kt][3], addr);
        }
    }

    float co[16][4];
    #pragma unroll
    for (int n = 0; n < 16; n++)
        #pragma unroll
        for (int r = 0; r < 4; r++) co[n][r] = 0.f;
    float m0 = -1e30f, m1 = -1e30f, l0 = 0.f, l1 = 0.f;

    for (int jt = 0; jt < ntk; jt++) {
        if (jt > 0) { CP_WAIT0(); __syncthreads(); }
        if (jt + 1 < ntk) { load_kv(jt + 1, (jt + 1) & 1); CP_COMMIT(); }

        const int buf = jt & 1;
        const uint32_t kbB = smb + (8704u + (uint32_t)buf * 17408u) * 2u;
        const uint32_t vbB = kbB + 8704u * 2u;

        float s[8][4];
        #pragma unroll
        for (int n = 0; n < 8; n++)
            #pragma unroll
            for (int r = 0; r < 4; r++) s[n][r] = 0.f;

        #pragma unroll
        for (int kt = 0; kt < 8; kt++) {
            #pragma unroll
            for (int np = 0; np < 4; np++) {
                uint32_t b0, b1, b2, b3;
                const uint32_t addr = kbB + (uint32_t)(
                    (np * 16 + ((lane >> 4) << 3) + (lane & 7)) * 136
                    + kt * 16 + ((lane >> 3) & 1) * 8) * 2;
                LDSM_X4(b0, b1, b2, b3, addr);
                MMA16816(s[2*np][0], s[2*np][1], s[2*np][2], s[2*np][3],
                         qa[kt][0], qa[kt][1], qa[kt][2], qa[kt][3], b0, b1);
                MMA16816(s[2*np+1][0], s[2*np+1][1], s[2*np+1][2], s[2*np+1][3],
                         qa[kt][0], qa[kt][1], qa[kt][2], qa[kt][3], b2, b3);
            }
        }

        if (jt == ntk - 1) {
            const int r0 = m0w + gid, r1 = r0 + 8;
            #pragma unroll
            for (int nt = 0; nt < 8; nt++) {
                const int c0 = nt * 8 + tig * 2, c1 = c0 + 1;
                if (c0 > r0) s[nt][0] = -1e30f;
                if (c1 > r0) s[nt][1] = -1e30f;
                if (c0 > r1) s[nt][2] = -1e30f;
                if (c1 > r1) s[nt][3] = -1e30f;
            }
        }

        float mx0 = -1e30f, mx1 = -1e30f;
        #pragma unroll
        for (int nt = 0; nt < 8; nt++) {
            mx0 = fmaxf(mx0, fmaxf(s[nt][0], s[nt][1]));
            mx1 = fmaxf(mx1, fmaxf(s[nt][2], s[nt][3]));
        }
        mx0 = fmaxf(mx0, __shfl_xor_sync(0xffffffffu, mx0, 1));
        mx0 = fmaxf(mx0, __shfl_xor_sync(0xffffffffu, mx0, 2));
        mx1 = fmaxf(mx1, __shfl_xor_sync(0xffffffffu, mx1, 1));
        mx1 = fmaxf(mx1, __shfl_xor_sync(0xffffffffu, mx1, 2));

        const float mn0 = fmaxf(m0, mx0), mn1 = fmaxf(m1, mx1);
        const float al0 = __expf(m0 - mn0), al1 = __expf(m1 - mn1);
        float ls0 = 0.f, ls1 = 0.f;
        #pragma unroll
        for (int nt = 0; nt < 8; nt++) {
            s[nt][0] = __expf(s[nt][0] - mn0);
            s[nt][1] = __expf(s[nt][1] - mn0);
            s[nt][2] = __expf(s[nt][2] - mn1);
            s[nt][3] = __expf(s[nt][3] - mn1);
            ls0 += s[nt][0] + s[nt][1];
            ls1 += s[nt][2] + s[nt][3];
        }
        ls0 += __shfl_xor_sync(0xffffffffu, ls0, 1);
        ls0 += __shfl_xor_sync(0xffffffffu, ls0, 2);
        ls1 += __shfl_xor_sync(0xffffffffu, ls1, 1);
        ls1 += __shfl_xor_sync(0xffffffffu, ls1, 2);
        l0 = l0 * al0 + ls0;  l1 = l1 * al1 + ls1;
        m0 = mn0;  m1 = mn1;

        #pragma unroll
        for (int nt = 0; nt < 16; nt++) {
            co[nt][0] *= al0; co[nt][1] *= al0;
            co[nt][2] *= al1; co[nt][3] *= al1;
        }

        uint32_t pa[4][4];
        #pragma unroll
        for (int t = 0; t < 4; t++) {
            pa[t][0] = pack_h2(s[2*t][0],   s[2*t][1]);
            pa[t][1] = pack_h2(s[2*t][2],   s[2*t][3]);
            pa[t][2] = pack_h2(s[2*t+1][0], s[2*t+1][1]);
            pa[t][3] = pack_h2(s[2*t+1][2], s[2*t+1][3]);
        }

        #pragma unroll
        for (int t = 0; t < 4; t++) {
            #pragma unroll
            for (int dp = 0; dp < 8; dp++) {
                uint32_t b0, b1, b2, b3;
                const uint32_t addr = vbB + (uint32_t)(
                    (t * 16 + ((lane >> 3) & 1) * 8 + (lane & 7)) * 136
                    + dp * 16 + (lane >> 4) * 8) * 2;
                LDSM_X4T(b0, b1, b2, b3, addr);
                MMA16816(co[2*dp][0], co[2*dp][1], co[2*dp][2], co[2*dp][3],
                         pa[t][0], pa[t][1], pa[t][2], pa[t][3], b0, b1);
                MMA16816(co[2*dp+1][0], co[2*dp+1][1], co[2*dp+1][2], co[2*dp+1][3],
                         pa[t][0], pa[t][1], pa[t][2], pa[t][3], b2, b3);
            }
        }
    }

    const float inv0 = 1.f / l0, inv1 = 1.f / l1;
    const int r0 = q0 + m0w + gid, r1 = r0 + 8;
    __half* o0 = ao + (size_t)(b * SB + r0) * NE + h * HD;
    __half* o1 = ao + (size_t)(b * SB + r1) * NE + h * HD;
    #pragma unroll
    for (int nt = 0; nt < 16; nt++) {
        const int cc = nt * 8 + tig * 2;
        *(__half2*)(o0 + cc) = __floats2half2_rn(co[nt][0] * inv0, co[nt][1] * inv0);
        *(__half2*)(o1 + cc) = __floats2half2_rn(co[nt][2] * inv1, co[nt][3] * inv1);
    }
}

// ---------------------------------------------------------------------------
extern "C" void kernel_launch(void* const* d_in, const int* in_sizes, int n_in,
                              void* d_out, int out_size)
{
    const float* x  = (const float*)d_in[0];
    const float* Wq = (const float*)d_in[1];
    const float* bq = (const float*)d_in[2];
    const float* Wk = (const float*)d_in[3];
    const float* bk = (const float*)d_in[4];
    const float* Wv = (const float*)d_in[5];
    const float* bv = (const float*)d_in[6];
    const float* Wo = (const float*)d_in[7];
    const float* bo = (const float*)d_in[8];
    float* out = (float*)d_out;

    __half *xh, *qkvh, *aoh, *wqkvh, *woh;
    float *bqkv;
    cudaGetSymbolAddress((void**)&xh,    g_xh);
    cudaGetSymbolAddress((void**)&qkvh,  g_qkvh);
    cudaGetSymbolAddress((void**)&aoh,   g_aoh);
    cudaGetSymbolAddress((void**)&wqkvh, g_wqkvh);
    cudaGetSymbolAddress((void**)&woh,   g_woh);
    cudaGetSymbolAddress((void**)&bqkv,  g_bqkv);

    cudaFuncSetAttribute(gemm_hmma64<__half>, cudaFuncAttributeMaxDynamicSharedMemorySize, GEMM_SMEM);
    cudaFuncSetAttribute(gemm_hmma64<float>,  cudaFuncAttributeMaxDynamicSharedMemorySize, GEMM_SMEM);
    cudaFuncSetAttribute(mqa_attn_h, cudaFuncAttributeMaxDynamicSharedMemorySize, ATT_SMEM);

    const float scale = 0.08838834764831845f;   // 1/sqrt(128)
    dim3 cblk(256);

    constexpr int WTOT = NQKV * NE + NE * NE;   // 4718592 + 4194304
    conv_weights<<<WTOT / 1024, cblk>>>(Wq, Wk, Wv, Wo, wqkvh, woh, scale);
    conv_bias<<<(NQKV + 255) / 256, cblk>>>(bq, bk, bv, bqkv, scale);
    conv_x<<<(MT * NE) / 1024, cblk>>>(x, xh, MT * NE);

    // fused Q|K|V projection: C[4096, 2304]
    gemm_hmma64<__half><<<dim3(NQKV / 128, MT / 128), dim3(128), GEMM_SMEM>>>(
        xh, wqkvh, bqkv, qkvh, MT, NQKV, NE);
    // attention (reads fused buffer)
    mqa_attn_h<<<dim3(SB / 64, NH, NB), dim3(128), ATT_SMEM>>>(qkvh, aoh);
    // output projection
    gemm_hmma64<float><<<dim3(NE / 128, MT / 128), dim3(128), GEMM_SMEM>>>(
        aoh, woh, bo, out, MT, NE, NE);
}

// round 8
// speedup vs baseline: 1.2527x; 1.0159x over previous
#include <cuda_runtime.h>
#include <cuda_fp16.h>
#include <cstdint>
#include <cstddef>

#define NE 2048
#define NH 16
#define HD 128
#define SB 2048
#define NB 2
#define MT 4096     // NB*SB
#define NQKV 2304   // 2048 (Q) + 128 (K) + 128 (V)

// ---------------- scratch (__device__ globals; no allocs) ------------------
__device__ __half g_xh   [MT * NE];
__device__ __half g_qkvh [MT * NQKV];      // fused Q|K|V, row stride 2304
__device__ __half g_aoh  [MT * NE];
__device__ __half g_wqkvh[NQKV * NE];
__device__ __half g_woh  [NE * NE];
__device__ float  g_bqkv [NQKV];

// ---------------- PTX helpers (sm_80-safe; no 'a' features) ----------------
#define CP16(sa, g)  asm volatile("cp.async.cg.shared.global [%0], [%1], 16;" :: "r"(sa), "l"(g))
#define CP_COMMIT()  asm volatile("cp.async.commit_group;" ::: "memory")
#define CP_WAIT1()   asm volatile("cp.async.wait_group 1;" ::: "memory")
#define CP_WAIT0()   asm volatile("cp.async.wait_group 0;" ::: "memory")

#define LDSM_X4(r0,r1,r2,r3, addr) \
    asm volatile("ldmatrix.sync.aligned.m8n8.x4.shared.b16 {%0,%1,%2,%3}, [%4];" \
        : "=r"(r0),"=r"(r1),"=r"(r2),"=r"(r3) : "r"(addr))
#define LDSM_X4T(r0,r1,r2,r3, addr) \
    asm volatile("ldmatrix.sync.aligned.m8n8.x4.trans.shared.b16 {%0,%1,%2,%3}, [%4];" \
        : "=r"(r0),"=r"(r1),"=r"(r2),"=r"(r3) : "r"(addr))
#define MMA16816(c0,c1,c2,c3, a0,a1,a2,a3, b0,b1) \
    asm volatile("mma.sync.aligned.m16n8k16.row.col.f32.f16.f16.f32 " \
        "{%0,%1,%2,%3}, {%4,%5,%6,%7}, {%8,%9}, {%0,%1,%2,%3};" \
        : "+f"(c0),"+f"(c1),"+f"(c2),"+f"(c3) \
        : "r"(a0),"r"(a1),"r"(a2),"r"(a3),"r"(b0),"r"(b1))

__device__ __forceinline__ uint32_t smem_u32(const void* p) {
    return (uint32_t)__cvta_generic_to_shared(p);
}
__device__ __forceinline__ uint32_t pack_h2(float a, float b) {
    __half2 h = __floats2half2_rn(a, b);
    return *(uint32_t*)&h;
}

// ---------------- fused conversion kernels ----------------------------------
__global__ void __launch_bounds__(256)
conv_weights(const float* __restrict__ Wq, const float* __restrict__ Wk,
             const float* __restrict__ Wv, const float* __restrict__ Wo,
             __half* __restrict__ wqkvh, __half* __restrict__ woh, float scale)
{
    constexpr int S0 = NE * NE;
    constexpr int S1 = S0 + HD * NE;
    constexpr int S2 = S1 + HD * NE;
    constexpr int S3 = S2 + NE * NE;
    const int i = (blockIdx.x * 256 + threadIdx.x) * 4;
    if (i < S0) {
        float4 v = *(const float4*)(Wq + i);
        __half2* o = (__half2*)(wqkvh + i);
        o[0] = __floats2half2_rn(v.x * scale, v.y * scale);
        o[1] = __floats2half2_rn(v.z * scale, v.w * scale);
    } else if (i < S1) {
        const int j = i - S0;
        float4 v = *(const float4*)(Wk + j);
        __half2* o = (__half2*)(wqkvh + NE * NE + j);
        o[0] = __floats2half2_rn(v.x, v.y);
        o[1] = __floats2half2_rn(v.z, v.w);
    } else if (i < S2) {
        const int j = i - S1;
        float4 v = *(const float4*)(Wv + j);
        __half2* o = (__half2*)(wqkvh + (NE + HD) * NE + j);
        o[0] = __floats2half2_rn(v.x, v.y);
        o[1] = __floats2half2_rn(v.z, v.w);
    } else if (i < S3) {
        const int j = i - S2;
        float4 v = *(const float4*)(Wo + j);
        __half2* o = (__half2*)(woh + j);
        o[0] = __floats2half2_rn(v.x, v.y);
        o[1] = __floats2half2_rn(v.z, v.w);
    }
}

__global__ void __launch_bounds__(256)
conv_bias(const float* __restrict__ bq, const float* __restrict__ bk,
          const float* __restrict__ bv, float* __restrict__ bqkv, float scale)
{
    const int t = blockIdx.x * 256 + threadIdx.x;
    if (t < NE) bqkv[t] = bq[t] * scale;
    else if (t < NE + HD) bqkv[t] = bk[t - NE];
    else if (t < NQKV) bqkv[t] = bv[t - NE - HD];
}

__global__ void __launch_bounds__(256)
conv_x(const float* __restrict__ in, __half* __restrict__ out, int n)
{
    int i = (blockIdx.x * 256 + threadIdx.x) * 4;
    if (i < n) {
        float4 v = *(const float4*)(in + i);
        __half2* o = (__half2*)(out + i);
        o[0] = __floats2half2_rn(v.x, v.y);
        o[1] = __floats2half2_rn(v.z, v.w);
    }
}

// ---------------------------------------------------------------------------
// HMMA GEMM: 128x128 CTA tile, 128 threads / 4 warps (2x2), warp tile 64x64,
// BK=32, 3-stage cp.async, 2 CTAs/SM. (validated R7)
// ---------------------------------------------------------------------------
#define PAD 40
#define STG (128 * PAD)
#define AOFF(st) ((st) * STG * 2)
#define BOFF(st) (3 * STG * 2 + (st) * STG * 2)
#define GEMM_SMEM (6 * STG * 2)

template<typename OutT>
__global__ void __launch_bounds__(128, 2)
gemm_hmma64(const __half* __restrict__ A, const __half* __restrict__ B,
            const float* __restrict__ bias, OutT* __restrict__ C,
            int M, int N, int K)
{
    extern __shared__ __half sh[];
    const uint32_t smb = smem_u32(sh);

    const int tid  = threadIdx.x;
    const int wid  = tid >> 5;
    const int lane = tid & 31;
    const int bm = blockIdx.y * 128;
    const int bn = blockIdx.x * 128;
    const int m0 = (wid >> 1) * 64;
    const int n0 = (wid & 1) * 64;

    const int lrow = tid >> 2;
    const int lch  = tid & 3;

    float c[4][8][4];
    #pragma unroll
    for (int mt = 0; mt < 4; mt++)
        #pragma unroll
        for (int nt = 0; nt < 8; nt++)
            #pragma unroll
            for (int r = 0; r < 4; r++) c[mt][nt][r] = 0.f;

    const __half* Ab = A + (size_t)bm * K;
    const __half* Bb = B + (size_t)bn * K;
    const int nk = K / 32;

    auto load_stage = [&](int st, int k0) {
        #pragma unroll
        for (int r = 0; r < 4; r++) {
            const int row = lrow + r * 32;
            const uint32_t so = (uint32_t)(row * PAD + lch * 8) * 2;
            CP16(smb + AOFF(st) + so, Ab + (size_t)row * K + k0 + lch * 8);
            CP16(smb + BOFF(st) + so, Bb + (size_t)row * K + k0 + lch * 8);
        }
    };

    load_stage(0, 0);  CP_COMMIT();
    load_stage(1, 32); CP_COMMIT();

    const int a_r = lane & 15, a_c = (lane >> 4) * 8;
    const int b_row = ((lane >> 4) << 3) + (lane & 7);
    const int b_col = ((lane >> 3) & 1) * 8;

    for (int i = 0; i < nk; i++) {
        CP_WAIT1();
        __syncthreads();
        if (i + 2 < nk) load_stage((i + 2) % 3, (i + 2) * 32);
        CP_COMMIT();

        const int st = i % 3;
        #pragma unroll
        for (int ks = 0; ks < 2; ks++) {
            uint32_t a[4][4], b[8][2];
            #pragma unroll
            for (int mt = 0; mt < 4; mt++) {
                const uint32_t addr = smb + AOFF(st) +
                    (uint32_t)((m0 + mt * 16 + a_r) * PAD + ks * 16 + a_c) * 2;
                LDSM_X4(a[mt][0], a[mt][1], a[mt][2], a[mt][3], addr);
            }
            #pragma unroll
            for (int np = 0; np < 4; np++) {
                const uint32_t addr = smb + BOFF(st) +
                    (uint32_t)((n0 + np * 16 + b_row) * PAD + ks * 16 + b_col) * 2;
                LDSM_X4(b[2*np][0], b[2*np][1], b[2*np+1][0], b[2*np+1][1], addr);
            }
            #pragma unroll
            for (int mt = 0; mt < 4; mt++)
                #pragma unroll
                for (int nt = 0; nt < 8; nt++)
                    MMA16816(c[mt][nt][0], c[mt][nt][1], c[mt][nt][2], c[mt][nt][3],
                             a[mt][0], a[mt][1], a[mt][2], a[mt][3],
                             b[nt][0], b[nt][1]);
        }
        __syncthreads();
    }

    const int tr  = lane >> 2;
    const int tc2 = (lane & 3) * 2;
    #pragma unroll
    for (int mt = 0; mt < 4; mt++) {
        const int r0 = bm + m0 + mt * 16 + tr;
        #pragma unroll
        for (int nt = 0; nt < 8; nt++) {
            const int cc = bn + n0 + nt * 8 + tc2;
            const float bx = bias[cc], by = bias[cc + 1];
            if constexpr (sizeof(OutT) == 4) {
                *(float2*)&C[(size_t)r0 * N + cc] =
                    make_float2(c[mt][nt][0] + bx, c[mt][nt][1] + by);
                *(float2*)&C[(size_t)(r0 + 8) * N + cc] =
                    make_float2(c[mt][nt][2] + bx, c[mt][nt][3] + by);
            } else {
                *(__half2*)&C[(size_t)r0 * N + cc] =
                    __floats2half2_rn(c[mt][nt][0] + bx, c[mt][nt][1] + by);
                *(__half2*)&C[(size_t)(r0 + 8) * N + cc] =
                    __floats2half2_rn(c[mt][nt][2] + bx, c[mt][nt][3] + by);
            }
        }
    }
}

// ---------------------------------------------------------------------------
// HMMA MQA flash attention v2: CTA = 128 q-rows, 4 warps x 32 rows each
// (two 16-row m-tiles). K/V fragments LDSMed once per warp feed 2x the MMAs
// vs v1 (port-bound fix). Q staged in SMEM, fragments re-loaded per tile.
// SMEM halves: Q[128][136] @0, then KV double buffer (K[64][136]+V[64][136]).
// ---------------------------------------------------------------------------
#define QSM   17408u                         // Q halves
#define KVSM  17408u                         // one KV buffer (K+V) halves
#define ATT_SMEM ((QSM + 2 * KVSM) * 2)      // 104448 B

__global__ void __launch_bounds__(128)
mqa_attn_h(const __half* __restrict__ qkv, __half* __restrict__ ao)
{
    extern __shared__ __half sh[];
    const uint32_t smb = smem_u32(sh);

    const int tid = threadIdx.x, wid = tid >> 5, lane = tid & 31;
    const int qt = gridDim.x - 1 - blockIdx.x;     // heavy tiles first
    const int h = blockIdx.y, b = blockIdx.z;
    const int q0 = qt * 128;
    const int ntk = 2 * qt + 2;                    // 64-wide kv tiles
    const int gid = lane >> 2, tig = lane & 3;
    const int m0w = wid * 32;                      // warp row base (32 rows)

    // ---- Q tile load: 128 rows x 128 cols fp16 ----
    {
        const __half* qg = qkv + (size_t)(b * SB + q0) * NQKV + h * HD;
        #pragma unroll
        for (int i = 0; i < 16; i++) {
            const int c = i * 128 + tid;
            const int row = c >> 4, ch = c & 15;
            CP16(smb + (uint32_t)(row * 136 + ch * 8) * 2,
                 qg + (size_t)row * NQKV + ch * 8);
        }
    }
    CP_COMMIT();

    auto load_kv = [&](int jt, int buf) {
        const __half* g = qkv + (size_t)(b * SB + jt * 64) * NQKV + NE;
        const uint32_t kb = QSM + (uint32_t)buf * KVSM;
        #pragma unroll
        for (int i = 0; i < 16; i++) {
            const int c = i * 128 + tid;
            const int row = c >> 5, ch = c & 31;
            const uint32_t off = kb + ((ch & 16) ? 8704u : 0u)
                               + (uint32_t)(row * 136 + (ch & 15) * 8);
            CP16(smb + off * 2, g + (size_t)row * NQKV + ch * 8);
        }
    };
    load_kv(0, 0);
    CP_COMMIT();
    CP_WAIT0();
    __syncthreads();

    float co[2][16][4];
    #pragma unroll
    for (int mt = 0; mt < 2; mt++)
        #pragma unroll
        for (int n = 0; n < 16; n++)
            #pragma unroll
            for (int r = 0; r < 4; r++) co[mt][n][r] = 0.f;
    float mrow[2][2] = {{-1e30f, -1e30f}, {-1e30f, -1e30f}};
    float lrow[2][2] = {{0.f, 0.f}, {0.f, 0.f}};

    const int a_r = lane & 15, a_c = (lane >> 4) * 8;
    const int k_row = ((lane >> 4) << 3) + (lane & 7);
    const int k_col = ((lane >> 3) & 1) * 8;

    for (int jt = 0; jt < ntk; jt++) {
        if (jt > 0) { CP_WAIT0(); __syncthreads(); }
        if (jt + 1 < ntk) { load_kv(jt + 1, (jt + 1) & 1); CP_COMMIT(); }

        const int buf = jt & 1;
        const uint32_t kbB = smb + (QSM + (uint32_t)buf * KVSM) * 2u;
        const uint32_t vbB = kbB + 8704u * 2u;

        // ---- S = Q K^T  (two m-tiles per warp; K loaded once) ----
        float s[2][8][4];
        #pragma unroll
        for (int mt = 0; mt < 2; mt++)
            #pragma unroll
            for (int n = 0; n < 8; n++)
                #pragma unroll
                for (int r = 0; r < 4; r++) s[mt][n][r] = 0.f;

        #pragma unroll
        for (int kt = 0; kt < 8; kt++) {
            uint32_t a0[4], a1[4];
            LDSM_X4(a0[0], a0[1], a0[2], a0[3], smb +
                (uint32_t)((m0w + a_r) * 136 + kt * 16 + a_c) * 2);
            LDSM_X4(a1[0], a1[1], a1[2], a1[3], smb +
                (uint32_t)((m0w + 16 + a_r) * 136 + kt * 16 + a_c) * 2);
            #pragma unroll
            for (int np = 0; np < 4; np++) {
                uint32_t b0, b1, b2, b3;
                const uint32_t addr = kbB + (uint32_t)(
                    (np * 16 + k_row) * 136 + kt * 16 + k_col) * 2;
                LDSM_X4(b0, b1, b2, b3, addr);
                MMA16816(s[0][2*np][0], s[0][2*np][1], s[0][2*np][2], s[0][2*np][3],
                         a0[0], a0[1], a0[2], a0[3], b0, b1);
                MMA16816(s[0][2*np+1][0], s[0][2*np+1][1], s[0][2*np+1][2], s[0][2*np+1][3],
                         a0[0], a0[1], a0[2], a0[3], b2, b3);
                MMA16816(s[1][2*np][0], s[1][2*np][1], s[1][2*np][2], s[1][2*np][3],
                         a1[0], a1[1], a1[2], a1[3], b0, b1);
                MMA16816(s[1][2*np+1][0], s[1][2*np+1][1], s[1][2*np+1][2], s[1][2*np+1][3],
                         a1[0], a1[1], a1[2], a1[3], b2, b3);
            }
        }

        // ---- causal mask (only last two tiles can straddle the diagonal) ----
        if (jt >= ntk - 2) {
            #pragma unroll
            for (int mt = 0; mt < 2; mt++) {
                const int rg0 = q0 + m0w + mt * 16 + gid;
                const int rg1 = rg0 + 8;
                #pragma unroll
                for (int nt = 0; nt < 8; nt++) {
                    const int cg0 = jt * 64 + nt * 8 + tig * 2;
                    const int cg1 = cg0 + 1;
                    if (cg0 > rg0) s[mt][nt][0] = -1e30f;
                    if (cg1 > rg0) s[mt][nt][1] = -1e30f;
                    if (cg0 > rg1) s[mt][nt][2] = -1e30f;
                    if (cg1 > rg1) s[mt][nt][3] = -1e30f;
                }
            }
        }

        // ---- online softmax (4 row-states: mt x half) ----
        float al[2][2];
        #pragma unroll
        for (int mt = 0; mt < 2; mt++) {
            float mx0 = -1e30f, mx1 = -1e30f;
            #pragma unroll
            for (int nt = 0; nt < 8; nt++) {
                mx0 = fmaxf(mx0, fmaxf(s[mt][nt][0], s[mt][nt][1]));
                mx1 = fmaxf(mx1, fmaxf(s[mt][nt][2], s[mt][nt][3]));
            }
            mx0 = fmaxf(mx0, __shfl_xor_sync(0xffffffffu, mx0, 1));
            mx0 = fmaxf(mx0, __shfl_xor_sync(0xffffffffu, mx0, 2));
            mx1 = fmaxf(mx1, __shfl_xor_sync(0xffffffffu, mx1, 1));
            mx1 = fmaxf(mx1, __shfl_xor_sync(0xffffffffu, mx1, 2));

            const float mn0 = fmaxf(mrow[mt][0], mx0);
            const float mn1 = fmaxf(mrow[mt][1], mx1);
            al[mt][0] = __expf(mrow[mt][0] - mn0);
            al[mt][1] = __expf(mrow[mt][1] - mn1);
            float ls0 = 0.f, ls1 = 0.f;
            #pragma unroll
            for (int nt = 0; nt < 8; nt++) {
                s[mt][nt][0] = __expf(s[mt][nt][0] - mn0);
                s[mt][nt][1] = __expf(s[mt][nt][1] - mn0);
                s[mt][nt][2] = __expf(s[mt][nt][2] - mn1);
                s[mt][nt][3] = __expf(s[mt][nt][3] - mn1);
                ls0 += s[mt][nt][0] + s[mt][nt][1];
                ls1 += s[mt][nt][2] + s[mt][nt][3];
            }
            ls0 += __shfl_xor_sync(0xffffffffu, ls0, 1);
            ls0 += __shfl_xor_sync(0xffffffffu, ls0, 2);
            ls1 += __shfl_xor_sync(0xffffffffu, ls1, 1);
            ls1 += __shfl_xor_sync(0xffffffffu, ls1, 2);
            lrow[mt][0] = lrow[mt][0] * al[mt][0] + ls0;
            lrow[mt][1] = lrow[mt][1] * al[mt][1] + ls1;
            mrow[mt][0] = mn0;
            mrow[mt][1] = mn1;

            #pragma unroll
            for (int nt = 0; nt < 16; nt++) {
                co[mt][nt][0] *= al[mt][0]; co[mt][nt][1] *= al[mt][0];
                co[mt][nt][2] *= al[mt][1]; co[mt][nt][3] *= al[mt][1];
            }
        }

        // ---- P fragments (register repack) ----
        uint32_t pa[2][4][4];
        #pragma unroll
        for (int mt = 0; mt < 2; mt++)
            #pragma unroll
            for (int t = 0; t < 4; t++) {
                pa[mt][t][0] = pack_h2(s[mt][2*t][0],   s[mt][2*t][1]);
                pa[mt][t][1] = pack_h2(s[mt][2*t][2],   s[mt][2*t][3]);
                pa[mt][t][2] = pack_h2(s[mt][2*t+1][0], s[mt][2*t+1][1]);
                pa[mt][t][3] = pack_h2(s[mt][2*t+1][2], s[mt][2*t+1][3]);
            }

        // ---- O += P V  (V loaded once per warp, shared by both m-tiles) ----
        #pragma unroll
        for (int t = 0; t < 4; t++) {
            #pragma unroll
            for (int dp = 0; dp < 8; dp++) {
                uint32_t b0, b1, b2, b3;
                const uint32_t addr = vbB + (uint32_t)(
                    (t * 16 + ((lane >> 3) & 1) * 8 + (lane & 7)) * 136
                    + dp * 16 + (lane >> 4) * 8) * 2;
                LDSM_X4T(b0, b1, b2, b3, addr);
                #pragma unroll
                for (int mt = 0; mt < 2; mt++) {
                    MMA16816(co[mt][2*dp][0], co[mt][2*dp][1],
                             co[mt][2*dp][2], co[mt][2*dp][3],
                             pa[mt][t][0], pa[mt][t][1], pa[mt][t][2], pa[mt][t][3],
                             b0, b1);
                    MMA16816(co[mt][2*dp+1][0], co[mt][2*dp+1][1],
                             co[mt][2*dp+1][2], co[mt][2*dp+1][3],
                             pa[mt][t][0], pa[mt][t][1], pa[mt][t][2], pa[mt][t][3],
                             b2, b3);
                }
            }
        }
    }

    // ---- finalize ----
    #pragma unroll
    for (int mt = 0; mt < 2; mt++) {
        const float inv0 = 1.f / lrow[mt][0], inv1 = 1.f / lrow[mt][1];
        const int r0 = q0 + m0w + mt * 16 + gid, r1 = r0 + 8;
        __half* o0 = ao + (size_t)(b * SB + r0) * NE + h * HD;
        __half* o1 = ao + (size_t)(b * SB + r1) * NE + h * HD;
        #pragma unroll
        for (int nt = 0; nt < 16; nt++) {
            const int cc = nt * 8 + tig * 2;
            *(__half2*)(o0 + cc) = __floats2half2_rn(co[mt][nt][0] * inv0,
                                                     co[mt][nt][1] * inv0);
            *(__half2*)(o1 + cc) = __floats2half2_rn(co[mt][nt][2] * inv1,
                                                     co[mt][nt][3] * inv1);
        }
    }
}

// ---------------------------------------------------------------------------
extern "C" void kernel_launch(void* const* d_in, const int* in_sizes, int n_in,
                              void* d_out, int out_size)
{
    const float* x  = (const float*)d_in[0];
    const float* Wq = (const float*)d_in[1];
    const float* bq = (const float*)d_in[2];
    const float* Wk = (const float*)d_in[3];
    const float* bk = (const float*)d_in[4];
    const float* Wv = (const float*)d_in[5];
    const float* bv = (const float*)d_in[6];
    const float* Wo = (const float*)d_in[7];
    const float* bo = (const float*)d_in[8];
    float* out = (float*)d_out;

    __half *xh, *qkvh, *aoh, *wqkvh, *woh;
    float *bqkv;
    cudaGetSymbolAddress((void**)&xh,    g_xh);
    cudaGetSymbolAddress((void**)&qkvh,  g_qkvh);
    cudaGetSymbolAddress((void**)&aoh,   g_aoh);
    cudaGetSymbolAddress((void**)&wqkvh, g_wqkvh);
    cudaGetSymbolAddress((void**)&woh,   g_woh);
    cudaGetSymbolAddress((void**)&bqkv,  g_bqkv);

    cudaFuncSetAttribute(gemm_hmma64<__half>, cudaFuncAttributeMaxDynamicSharedMemorySize, GEMM_SMEM);
    cudaFuncSetAttribute(gemm_hmma64<float>,  cudaFuncAttributeMaxDynamicSharedMemorySize, GEMM_SMEM);
    cudaFuncSetAttribute(mqa_attn_h, cudaFuncAttributeMaxDynamicSharedMemorySize, ATT_SMEM);

    const float scale = 0.08838834764831845f;   // 1/sqrt(128)
    dim3 cblk(256);

    constexpr int WTOT = NQKV * NE + NE * NE;
    conv_weights<<<WTOT / 1024, cblk>>>(Wq, Wk, Wv, Wo, wqkvh, woh, scale);
    conv_bias<<<(NQKV + 255) / 256, cblk>>>(bq, bk, bv, bqkv, scale);
    conv_x<<<(MT * NE) / 1024, cblk>>>(x, xh, MT * NE);

    // fused Q|K|V projection
    gemm_hmma64<__half><<<dim3(NQKV / 128, MT / 128), dim3(128), GEMM_SMEM>>>(
        xh, wqkvh, bqkv, qkvh, MT, NQKV, NE);
    // attention (128 q-rows per CTA)
    mqa_attn_h<<<dim3(SB / 128, NH, NB), dim3(128), ATT_SMEM>>>(qkvh, aoh);
    // output projection
    gemm_hmma64<float><<<dim3(NE / 128, MT / 128), dim3(128), GEMM_SMEM>>>(
        aoh, woh, bo, out, MT, NE, NE);
}

// round 9
// speedup vs baseline: 1.3048x; 1.0416x over previous
#include <cuda_runtime.h>
#include <cuda_fp16.h>
#include <cstdint>
#include <cstddef>

#define NE 2048
#define NH 16
#define HD 128
#define SB 2048
#define NB 2
#define MT 4096     // NB*SB
#define NQKV 2304   // 2048 (Q) + 128 (K) + 128 (V)

// ---------------- scratch (__device__ globals; no allocs) ------------------
__device__ __half g_xh   [MT * NE];
__device__ __half g_qkvh [MT * NQKV];      // fused Q|K|V, row stride 2304
__device__ __half g_aoh  [MT * NE];
__device__ __half g_wqkvh[NQKV * NE];
__device__ __half g_woh  [NE * NE];
__device__ float  g_bqkv [NQKV];

// ---------------- PTX helpers (sm_80-safe; no 'a' features) ----------------
#define CP16(sa, g)  asm volatile("cp.async.cg.shared.global [%0], [%1], 16;" :: "r"(sa), "l"(g))
#define CP_COMMIT()  asm volatile("cp.async.commit_group;" ::: "memory")
#define CP_WAIT1()   asm volatile("cp.async.wait_group 1;" ::: "memory")
#define CP_WAIT0()   asm volatile("cp.async.wait_group 0;" ::: "memory")

#define LDSM_X4(r0,r1,r2,r3, addr) \
    asm volatile("ldmatrix.sync.aligned.m8n8.x4.shared.b16 {%0,%1,%2,%3}, [%4];" \
        : "=r"(r0),"=r"(r1),"=r"(r2),"=r"(r3) : "r"(addr))
#define LDSM_X4T(r0,r1,r2,r3, addr) \
    asm volatile("ldmatrix.sync.aligned.m8n8.x4.trans.shared.b16 {%0,%1,%2,%3}, [%4];" \
        : "=r"(r0),"=r"(r1),"=r"(r2),"=r"(r3) : "r"(addr))
#define LDSM_X2T(r0,r1, addr) \
    asm volatile("ldmatrix.sync.aligned.m8n8.x2.trans.shared.b16 {%0,%1}, [%2];" \
        : "=r"(r0),"=r"(r1) : "r"(addr))
#define MMA16816(c0,c1,c2,c3, a0,a1,a2,a3, b0,b1) \
    asm volatile("mma.sync.aligned.m16n8k16.row.col.f32.f16.f16.f32 " \
        "{%0,%1,%2,%3}, {%4,%5,%6,%7}, {%8,%9}, {%0,%1,%2,%3};" \
        : "+f"(c0),"+f"(c1),"+f"(c2),"+f"(c3) \
        : "r"(a0),"r"(a1),"r"(a2),"r"(a3),"r"(b0),"r"(b1))
#define EX2H2(x) asm volatile("ex2.approx.f16x2 %0, %0;" : "+r"(x))

__device__ __forceinline__ uint32_t smem_u32(const void* p) {
    return (uint32_t)__cvta_generic_to_shared(p);
}
__device__ __forceinline__ uint32_t pack_h2(float a, float b) {
    __half2 h = __floats2half2_rn(a, b);
    return *(uint32_t*)&h;
}
__device__ __forceinline__ float ex2f(float x) {
    float y;
    asm("ex2.approx.ftz.f32 %0, %1;" : "=f"(y) : "f"(x));
    return y;
}

// ---------------- fused conversion kernels ----------------------------------
// Q weights/bias scaled by (1/sqrt(HD)) * log2(e): logits land in log2 domain.
__global__ void __launch_bounds__(256)
conv_weights(const float* __restrict__ Wq, const float* __restrict__ Wk,
             const float* __restrict__ Wv, const float* __restrict__ Wo,
             __half* __restrict__ wqkvh, __half* __restrict__ woh, float scale)
{
    constexpr int S0 = NE * NE;
    constexpr int S1 = S0 + HD * NE;
    constexpr int S2 = S1 + HD * NE;
    constexpr int S3 = S2 + NE * NE;
    const int i = (blockIdx.x * 256 + threadIdx.x) * 4;
    if (i < S0) {
        float4 v = *(const float4*)(Wq + i);
        __half2* o = (__half2*)(wqkvh + i);
        o[0] = __floats2half2_rn(v.x * scale, v.y * scale);
        o[1] = __floats2half2_rn(v.z * scale, v.w * scale);
    } else if (i < S1) {
        const int j = i - S0;
        float4 v = *(const float4*)(Wk + j);
        __half2* o = (__half2*)(wqkvh + NE * NE + j);
        o[0] = __floats2half2_rn(v.x, v.y);
        o[1] = __floats2half2_rn(v.z, v.w);
    } else if (i < S2) {
        const int j = i - S1;
        float4 v = *(const float4*)(Wv + j);
        __half2* o = (__half2*)(wqkvh + (NE + HD) * NE + j);
        o[0] = __floats2half2_rn(v.x, v.y);
        o[1] = __floats2half2_rn(v.z, v.w);
    } else if (i < S3) {
        const int j = i - S2;
        float4 v = *(const float4*)(Wo + j);
        __half2* o = (__half2*)(woh + j);
        o[0] = __floats2half2_rn(v.x, v.y);
        o[1] = __floats2half2_rn(v.z, v.w);
    }
}

__global__ void __launch_bounds__(256)
conv_bias(const float* __restrict__ bq, const float* __restrict__ bk,
          const float* __restrict__ bv, float* __restrict__ bqkv, float scale)
{
    const int t = blockIdx.x * 256 + threadIdx.x;
    if (t < NE) bqkv[t] = bq[t] * scale;
    else if (t < NE + HD) bqkv[t] = bk[t - NE];
    else if (t < NQKV) bqkv[t] = bv[t - NE - HD];
}

__global__ void __launch_bounds__(256)
conv_x(const float* __restrict__ in, __half* __restrict__ out, int n)
{
    int i = (blockIdx.x * 256 + threadIdx.x) * 4;
    if (i < n) {
        float4 v = *(const float4*)(in + i);
        __half2* o = (__half2*)(out + i);
        o[0] = __floats2half2_rn(v.x, v.y);
        o[1] = __floats2half2_rn(v.z, v.w);
    }
}

// ---------------------------------------------------------------------------
// HMMA GEMM: 128x128 CTA tile, 128 threads / 4 warps (2x2), warp tile 64x64,
// BK=32, 3-stage cp.async, 2 CTAs/SM. (validated R7/R8)
// ---------------------------------------------------------------------------
#define PAD 40
#define STG (128 * PAD)
#define AOFF(st) ((st) * STG * 2)
#define BOFF(st) (3 * STG * 2 + (st) * STG * 2)
#define GEMM_SMEM (6 * STG * 2)

template<typename OutT>
__global__ void __launch_bounds__(128, 2)
gemm_hmma64(const __half* __restrict__ A, const __half* __restrict__ B,
            const float* __restrict__ bias, OutT* __restrict__ C,
            int M, int N, int K)
{
    extern __shared__ __half sh[];
    const uint32_t smb = smem_u32(sh);

    const int tid  = threadIdx.x;
    const int wid  = tid >> 5;
    const int lane = tid & 31;
    const int bm = blockIdx.y * 128;
    const int bn = blockIdx.x * 128;
    const int m0 = (wid >> 1) * 64;
    const int n0 = (wid & 1) * 64;

    const int lrow = tid >> 2;
    const int lch  = tid & 3;

    float c[4][8][4];
    #pragma unroll
    for (int mt = 0; mt < 4; mt++)
        #pragma unroll
        for (int nt = 0; nt < 8; nt++)
            #pragma unroll
            for (int r = 0; r < 4; r++) c[mt][nt][r] = 0.f;

    const __half* Ab = A + (size_t)bm * K;
    const __half* Bb = B + (size_t)bn * K;
    const int nk = K / 32;

    auto load_stage = [&](int st, int k0) {
        #pragma unroll
        for (int r = 0; r < 4; r++) {
            const int row = lrow + r * 32;
            const uint32_t so = (uint32_t)(row * PAD + lch * 8) * 2;
            CP16(smb + AOFF(st) + so, Ab + (size_t)row * K + k0 + lch * 8);
            CP16(smb + BOFF(st) + so, Bb + (size_t)row * K + k0 + lch * 8);
        }
    };

    load_stage(0, 0);  CP_COMMIT();
    load_stage(1, 32); CP_COMMIT();

    const int a_r = lane & 15, a_c = (lane >> 4) * 8;
    const int b_row = ((lane >> 4) << 3) + (lane & 7);
    const int b_col = ((lane >> 3) & 1) * 8;

    for (int i = 0; i < nk; i++) {
        CP_WAIT1();
        __syncthreads();
        if (i + 2 < nk) load_stage((i + 2) % 3, (i + 2) * 32);
        CP_COMMIT();

        const int st = i % 3;
        #pragma unroll
        for (int ks = 0; ks < 2; ks++) {
            uint32_t a[4][4], b[8][2];
            #pragma unroll
            for (int mt = 0; mt < 4; mt++) {
                const uint32_t addr = smb + AOFF(st) +
                    (uint32_t)((m0 + mt * 16 + a_r) * PAD + ks * 16 + a_c) * 2;
                LDSM_X4(a[mt][0], a[mt][1], a[mt][2], a[mt][3], addr);
            }
            #pragma unroll
            for (int np = 0; np < 4; np++) {
                const uint32_t addr = smb + BOFF(st) +
                    (uint32_t)((n0 + np * 16 + b_row) * PAD + ks * 16 + b_col) * 2;
                LDSM_X4(b[2*np][0], b[2*np][1], b[2*np+1][0], b[2*np+1][1], addr);
            }
            #pragma unroll
            for (int mt = 0; mt < 4; mt++)
                #pragma unroll
                for (int nt = 0; nt < 8; nt++)
                    MMA16816(c[mt][nt][0], c[mt][nt][1], c[mt][nt][2], c[mt][nt][3],
                             a[mt][0], a[mt][1], a[mt][2], a[mt][3],
                             b[nt][0], b[nt][1]);
        }
        __syncthreads();
    }

    const int tr  = lane >> 2;
    const int tc2 = (lane & 3) * 2;
    #pragma unroll
    for (int mt = 0; mt < 4; mt++) {
        const int r0 = bm + m0 + mt * 16 + tr;
        #pragma unroll
        for (int nt = 0; nt < 8; nt++) {
            const int cc = bn + n0 + nt * 8 + tc2;
            const float bx = bias[cc], by = bias[cc + 1];
            if constexpr (sizeof(OutT) == 4) {
                *(float2*)&C[(size_t)r0 * N + cc] =
                    make_float2(c[mt][nt][0] + bx, c[mt][nt][1] + by);
                *(float2*)&C[(size_t)(r0 + 8) * N + cc] =
                    make_float2(c[mt][nt][2] + bx, c[mt][nt][3] + by);
            } else {
                *(__half2*)&C[(size_t)r0 * N + cc] =
                    __floats2half2_rn(c[mt][nt][0] + bx, c[mt][nt][1] + by);
                *(__half2*)&C[(size_t)(r0 + 8) * N + cc] =
                    __floats2half2_rn(c[mt][nt][2] + bx, c[mt][nt][3] + by);
            }
        }
    }
}

// ---------------------------------------------------------------------------
// HMMA MQA flash attention v3: 128 q-rows/CTA, 4 warps x 32 rows.
// log2-domain logits; exp via ex2.approx.f16x2 (P emerges pre-packed);
// row-sum l accumulated by an extra PV MMA against a ones-column in V pad.
// ---------------------------------------------------------------------------
#define QSM   17408u                         // Q halves (128 x 136)
#define KVSM  17408u                         // one KV buffer (K+V) halves
#define ATT_SMEM ((QSM + 2 * KVSM) * 2)      // 104448 B

__global__ void __launch_bounds__(128)
mqa_attn_h(const __half* __restrict__ qkv, __half* __restrict__ ao)
{
    extern __shared__ __half sh[];
    const uint32_t smb = smem_u32(sh);

    const int tid = threadIdx.x, wid = tid >> 5, lane = tid & 31;
    const int qt = gridDim.x - 1 - blockIdx.x;     // heavy tiles first
    const int h = blockIdx.y, b = blockIdx.z;
    const int q0 = qt * 128;
    const int ntk = 2 * qt + 2;                    // 64-wide kv tiles
    const int gid = lane >> 2, tig = lane & 3;
    const int m0w = wid * 32;

    // ---- Q tile load ----
    {
        const __half* qg = qkv + (size_t)(b * SB + q0) * NQKV + h * HD;
        #pragma unroll
        for (int i = 0; i < 16; i++) {
            const int c = i * 128 + tid;
            const int row = c >> 4, ch = c & 15;
            CP16(smb + (uint32_t)(row * 136 + ch * 8) * 2,
                 qg + (size_t)row * NQKV + ch * 8);
        }
    }
    CP_COMMIT();

    auto load_kv = [&](int jt, int buf) {
        const __half* g = qkv + (size_t)(b * SB + jt * 64) * NQKV + NE;
        const uint32_t kb = QSM + (uint32_t)buf * KVSM;
        #pragma unroll
        for (int i = 0; i < 16; i++) {
            const int c = i * 128 + tid;
            const int row = c >> 5, ch = c & 31;
            const uint32_t off = kb + ((ch & 16) ? 8704u : 0u)
                               + (uint32_t)(row * 136 + (ch & 15) * 8);
            CP16(smb + off * 2, g + (size_t)row * NQKV + ch * 8);
        }
    };
    load_kv(0, 0);
    CP_COMMIT();

    // ---- ones-column init in V pad (cols 128..135): written ONCE; cp.async
    // never touches these columns, so it persists across all tiles. ----
    if (tid < 64) {
        uint4 onev = make_uint4(0x00003C00u, 0u, 0u, 0u);  // {1.0h, 0...0}
        *(uint4*)(sh + QSM + 8704u + (uint32_t)tid * 136u + 128u) = onev;
        *(uint4*)(sh + QSM + KVSM + 8704u + (uint32_t)tid * 136u + 128u) = onev;
    }
    CP_WAIT0();
    __syncthreads();

    float co[2][16][4];
    float cl[2][4];
    #pragma unroll
    for (int mt = 0; mt < 2; mt++) {
        #pragma unroll
        for (int n = 0; n < 16; n++)
            #pragma unroll
            for (int r = 0; r < 4; r++) co[mt][n][r] = 0.f;
        #pragma unroll
        for (int r = 0; r < 4; r++) cl[mt][r] = 0.f;
    }
    float mrow[2][2] = {{-1e30f, -1e30f}, {-1e30f, -1e30f}};

    const int a_r = lane & 15, a_c = (lane >> 4) * 8;
    const int k_row = ((lane >> 4) << 3) + (lane & 7);
    const int k_col = ((lane >> 3) & 1) * 8;

    for (int jt = 0; jt < ntk; jt++) {
        if (jt > 0) { CP_WAIT0(); __syncthreads(); }
        if (jt + 1 < ntk) { load_kv(jt + 1, (jt + 1) & 1); CP_COMMIT(); }

        const int buf = jt & 1;
        const uint32_t kbB = smb + (QSM + (uint32_t)buf * KVSM) * 2u;
        const uint32_t vbB = kbB + 8704u * 2u;

        // ---- S = Q K^T (log2-domain logits; K fragments loaded once) ----
        float s[2][8][4];
        #pragma unroll
        for (int mt = 0; mt < 2; mt++)
            #pragma unroll
            for (int n = 0; n < 8; n++)
                #pragma unroll
                for (int r = 0; r < 4; r++) s[mt][n][r] = 0.f;

        #pragma unroll
        for (int kt = 0; kt < 8; kt++) {
            uint32_t a0[4], a1[4];
            LDSM_X4(a0[0], a0[1], a0[2], a0[3], smb +
                (uint32_t)((m0w + a_r) * 136 + kt * 16 + a_c) * 2);
            LDSM_X4(a1[0], a1[1], a1[2], a1[3], smb +
                (uint32_t)((m0w + 16 + a_r) * 136 + kt * 16 + a_c) * 2);
            #pragma unroll
            for (int np = 0; np < 4; np++) {
                uint32_t b0, b1, b2, b3;
                const uint32_t addr = kbB + (uint32_t)(
                    (np * 16 + k_row) * 136 + kt * 16 + k_col) * 2;
                LDSM_X4(b0, b1, b2, b3, addr);
                MMA16816(s[0][2*np][0], s[0][2*np][1], s[0][2*np][2], s[0][2*np][3],
                         a0[0], a0[1], a0[2], a0[3], b0, b1);
                MMA16816(s[0][2*np+1][0], s[0][2*np+1][1], s[0][2*np+1][2], s[0][2*np+1][3],
                         a0[0], a0[1], a0[2], a0[3], b2, b3);
                MMA16816(s[1][2*np][0], s[1][2*np][1], s[1][2*np][2], s[1][2*np][3],
                         a1[0], a1[1], a1[2], a1[3], b0, b1);
                MMA16816(s[1][2*np+1][0], s[1][2*np+1][1], s[1][2*np+1][2], s[1][2*np+1][3],
                         a1[0], a1[1], a1[2], a1[3], b2, b3);
            }
        }

        // ---- causal mask ----
        if (jt >= ntk - 2) {
            #pragma unroll
            for (int mt = 0; mt < 2; mt++) {
                const int rg0 = q0 + m0w + mt * 16 + gid;
                const int rg1 = rg0 + 8;
                #pragma unroll
                for (int nt = 0; nt < 8; nt++) {
                    const int cg0 = jt * 64 + nt * 8 + tig * 2;
                    const int cg1 = cg0 + 1;
                    if (cg0 > rg0) s[mt][nt][0] = -1e30f;
                    if (cg1 > rg0) s[mt][nt][1] = -1e30f;
                    if (cg0 > rg1) s[mt][nt][2] = -1e30f;
                    if (cg1 > rg1) s[mt][nt][3] = -1e30f;
                }
            }
        }

        // ---- online softmax (log2-domain; P emerges packed fp16x2) ----
        uint32_t pa[2][4][4];
        #pragma unroll
        for (int mt = 0; mt < 2; mt++) {
            float mx0 = -1e30f, mx1 = -1e30f;
            #pragma unroll
            for (int nt = 0; nt < 8; nt++) {
                mx0 = fmaxf(mx0, fmaxf(s[mt][nt][0], s[mt][nt][1]));
                mx1 = fmaxf(mx1, fmaxf(s[mt][nt][2], s[mt][nt][3]));
            }
            mx0 = fmaxf(mx0, __shfl_xor_sync(0xffffffffu, mx0, 1));
            mx0 = fmaxf(mx0, __shfl_xor_sync(0xffffffffu, mx0, 2));
            mx1 = fmaxf(mx1, __shfl_xor_sync(0xffffffffu, mx1, 1));
            mx1 = fmaxf(mx1, __shfl_xor_sync(0xffffffffu, mx1, 2));

            const float mn0 = fmaxf(mrow[mt][0], mx0);
            const float mn1 = fmaxf(mrow[mt][1], mx1);
            const float al0 = ex2f(mrow[mt][0] - mn0);
            const float al1 = ex2f(mrow[mt][1] - mn1);
            mrow[mt][0] = mn0;
            mrow[mt][1] = mn1;

            #pragma unroll
            for (int nt = 0; nt < 8; nt++) {
                uint32_t p0 = pack_h2(s[mt][nt][0] - mn0, s[mt][nt][1] - mn0);
                uint32_t p1 = pack_h2(s[mt][nt][2] - mn1, s[mt][nt][3] - mn1);
                EX2H2(p0);
                EX2H2(p1);
                pa[mt][nt >> 1][(nt & 1) * 2]     = p0;
                pa[mt][nt >> 1][(nt & 1) * 2 + 1] = p1;
            }

            #pragma unroll
            for (int nt = 0; nt < 16; nt++) {
                co[mt][nt][0] *= al0; co[mt][nt][1] *= al0;
                co[mt][nt][2] *= al1; co[mt][nt][3] *= al1;
            }
            cl[mt][0] *= al0; cl[mt][1] *= al0;
            cl[mt][2] *= al1; cl[mt][3] *= al1;
        }

        // ---- O += P V ; l accumulates via ones-column MMA ----
        #pragma unroll
        for (int t = 0; t < 4; t++) {
            #pragma unroll
            for (int dp = 0; dp < 8; dp++) {
                uint32_t b0, b1, b2, b3;
                const uint32_t addr = vbB + (uint32_t)(
                    (t * 16 + ((lane >> 3) & 1) * 8 + (lane & 7)) * 136
                    + dp * 16 + (lane >> 4) * 8) * 2;
                LDSM_X4T(b0, b1, b2, b3, addr);
                #pragma unroll
                for (int mt = 0; mt < 2; mt++) {
                    MMA16816(co[mt][2*dp][0], co[mt][2*dp][1],
                             co[mt][2*dp][2], co[mt][2*dp][3],
                             pa[mt][t][0], pa[mt][t][1], pa[mt][t][2], pa[mt][t][3],
                             b0, b1);
                    MMA16816(co[mt][2*dp+1][0], co[mt][2*dp+1][1],
                             co[mt][2*dp+1][2], co[mt][2*dp+1][3],
                             pa[mt][t][0], pa[mt][t][1], pa[mt][t][2], pa[mt][t][3],
                             b2, b3);
                }
            }
            // ones-column block (V cols 128..135): row-sum -> cl
            {
                uint32_t e0, e1;
                const uint32_t oaddr = vbB + (uint32_t)(
                    (t * 16 + ((lane >> 3) & 1) * 8 + (lane & 7)) * 136 + 128) * 2;
                LDSM_X2T(e0, e1, oaddr);
                #pragma unroll
                for (int mt = 0; mt < 2; mt++)
                    MMA16816(cl[mt][0], cl[mt][1], cl[mt][2], cl[mt][3],
                             pa[mt][t][0], pa[mt][t][1], pa[mt][t][2], pa[mt][t][3],
                             e0, e1);
            }
        }
    }

    // ---- finalize: l lives at tig==0 (V col 128); broadcast within quad ----
    #pragma unroll
    for (int mt = 0; mt < 2; mt++) {
        const float l0 = __shfl_sync(0xffffffffu, cl[mt][0], lane & 28);
        const float l1 = __shfl_sync(0xffffffffu, cl[mt][2], lane & 28);
        const float inv0 = 1.f / l0, inv1 = 1.f / l1;
        const int r0 = q0 + m0w + mt * 16 + gid, r1 = r0 + 8;
        __half* o0 = ao + (size_t)(b * SB + r0) * NE + h * HD;
        __half* o1 = ao + (size_t)(b * SB + r1) * NE + h * HD;
        #pragma unroll
        for (int nt = 0; nt < 16; nt++) {
            const int cc = nt * 8 + tig * 2;
            *(__half2*)(o0 + cc) = __floats2half2_rn(co[mt][nt][0] * inv0,
                                                     co[mt][nt][1] * inv0);
            *(__half2*)(o1 + cc) = __floats2half2_rn(co[mt][nt][2] * inv1,
                                                     co[mt][nt][3] * inv1);
        }
    }
}

// ---------------------------------------------------------------------------
extern "C" void kernel_launch(void* const* d_in, const int* in_sizes, int n_in,
                              void* d_out, int out_size)
{
    const float* x  = (const float*)d_in[0];
    const float* Wq = (const float*)d_in[1];
    const float* bq = (const float*)d_in[2];
    const float* Wk = (const float*)d_in[3];
    const float* bk = (const float*)d_in[4];
    const float* Wv = (const float*)d_in[5];
    const float* bv = (const float*)d_in[6];
    const float* Wo = (const float*)d_in[7];
    const float* bo = (const float*)d_in[8];
    float* out = (float*)d_out;

    __half *xh, *qkvh, *aoh, *wqkvh, *woh;
    float *bqkv;
    cudaGetSymbolAddress((void**)&xh,    g_xh);
    cudaGetSymbolAddress((void**)&qkvh,  g_qkvh);
    cudaGetSymbolAddress((void**)&aoh,   g_aoh);
    cudaGetSymbolAddress((void**)&wqkvh, g_wqkvh);
    cudaGetSymbolAddress((void**)&woh,   g_woh);
    cudaGetSymbolAddress((void**)&bqkv,  g_bqkv);

    cudaFuncSetAttribute(gemm_hmma64<__half>, cudaFuncAttributeMaxDynamicSharedMemorySize, GEMM_SMEM);
    cudaFuncSetAttribute(gemm_hmma64<float>,  cudaFuncAttributeMaxDynamicSharedMemorySize, GEMM_SMEM);
    cudaFuncSetAttribute(mqa_attn_h, cudaFuncAttributeMaxDynamicSharedMemorySize, ATT_SMEM);

    // 1/sqrt(128) * log2(e): logits in log2 domain
    const float scale = 0.08838834764831845f * 1.4426950408889634f;
    dim3 cblk(256);

    constexpr int WTOT = NQKV * NE + NE * NE;
    conv_weights<<<WTOT / 1024, cblk>>>(Wq, Wk, Wv, Wo, wqkvh, woh, scale);
    conv_bias<<<(NQKV + 255) / 256, cblk>>>(bq, bk, bv, bqkv, scale);
    conv_x<<<(MT * NE) / 1024, cblk>>>(x, xh, MT * NE);

    gemm_hmma64<__half><<<dim3(NQKV / 128, MT / 128), dim3(128), GEMM_SMEM>>>(
        xh, wqkvh, bqkv, qkvh, MT, NQKV, NE);
    mqa_attn_h<<<dim3(SB / 128, NH, NB), dim3(128), ATT_SMEM>>>(qkvh, aoh);
    gemm_hmma64<float><<<dim3(NE / 128, MT / 128), dim3(128), GEMM_SMEM>>>(
        aoh, woh, bo, out, MT, NE, NE);
}